// round 9
// baseline (speedup 1.0000x reference)
#include <cuda_runtime.h>
#include <cuda_fp16.h>

#define NU 100000
#define NI 50000
#define NE 1600000
#define D  128
#define HNU 50000   // user chunk size

// ---------------- scratch (device globals) ----------------------------------
__device__ int g_h_fs[NU];
__device__ int g_h_fd[NU];
__device__ int g_h_rs[NU];
__device__ int g_h_rd[NI];
__device__ int g_h_vs[NI];
__device__ int g_h_vd[NU];

__device__ float g_inv_fs[NU];
__device__ float g_inv_fd[NU];
__device__ float g_inv_rs[NU];
__device__ float g_inv_rd[NI];
__device__ float g_inv_vs[NI];
__device__ float g_inv_vd[NU];

__device__ int   g_off_f[NU + 1];
__device__ int   g_off_r[NI + 1];
__device__ int   g_off_v[NU + 1];
__device__ int   g_pos_f[NU];
__device__ int   g_pos_r[NI];
__device__ int   g_pos_v[NU];
__device__ int2  g_ef[NE];
__device__ int2  g_er[NE];
__device__ int2  g_ev[NE];
__device__ int   g_bsum[3][1024];

__device__ __half g_hu1[(size_t)NU * D];
__device__ __half g_hu2[(size_t)NU * D];
__device__ __half g_hi [(size_t)NI * D];
__device__ __half g_hu1b[(size_t)NU * D];
__device__ __half g_hu2b[(size_t)NU * D];
__device__ __half g_hib [(size_t)NI * D];
__device__ float  g_u  [(size_t)NU * D];
__device__ float  g_it [(size_t)NI * D];

// ---------------- setup kernels ----------------------------------------------

__global__ void k_zero_hists() {
    int i = blockIdx.x * blockDim.x + threadIdx.x;
    if (i < NU) { g_h_fs[i] = 0; g_h_fd[i] = 0; g_h_rs[i] = 0; g_h_vd[i] = 0; }
    if (i < NI) { g_h_rd[i] = 0; g_h_vs[i] = 0; }
}

__global__ void k_hist3(const int* __restrict__ fs, const int* __restrict__ fd,
                        const int* __restrict__ rs, const int* __restrict__ rd,
                        const int* __restrict__ vs, const int* __restrict__ vd) {
    int e = blockIdx.x * blockDim.x + threadIdx.x;
    if (e >= NE) return;
    if (blockIdx.y == 0) {
        atomicAdd(&g_h_fs[fs[e]], 1);
        atomicAdd(&g_h_fd[fd[e]], 1);
    } else if (blockIdx.y == 1) {
        atomicAdd(&g_h_rs[rs[e]], 1);
        atomicAdd(&g_h_rd[rd[e]], 1);
    } else {
        atomicAdd(&g_h_vs[vs[e]], 1);
        atomicAdd(&g_h_vd[vd[e]], 1);
    }
}

__device__ __forceinline__ float invsq(int x) {
    return x > 0 ? rsqrtf((float)x) : 0.f;
}

__global__ void k_inv_all() {
    int i = blockIdx.x * blockDim.x + threadIdx.x;
    if (i < NU) {
        g_inv_fs[i] = invsq(g_h_fs[i]);
        g_inv_fd[i] = invsq(g_h_fd[i]);
        g_inv_rs[i] = invsq(g_h_rs[i]);
        g_inv_vd[i] = invsq(g_h_vd[i]);
    }
    if (i < NI) {
        g_inv_rd[i] = invsq(g_h_rd[i]);
        g_inv_vs[i] = invsq(g_h_vs[i]);
    }
}

__global__ void k_scan1() {
    __shared__ int s[1024];
    const int* in; int* outp; int n;
    if (blockIdx.y == 0)      { in = g_h_fd; outp = g_off_f; n = NU; }
    else if (blockIdx.y == 1) { in = g_h_rd; outp = g_off_r; n = NI; }
    else                      { in = g_h_vd; outp = g_off_v; n = NU; }
    int tid = threadIdx.x;
    int i = blockIdx.x * 1024 + tid;
    int v = (i < n) ? in[i] : 0;
    s[tid] = v;
    __syncthreads();
#pragma unroll
    for (int o = 1; o < 1024; o <<= 1) {
        int t = (tid >= o) ? s[tid - o] : 0;
        __syncthreads();
        s[tid] += t;
        __syncthreads();
    }
    if (i < n) outp[i] = s[tid] - v;
    if (tid == 1023) g_bsum[blockIdx.y][blockIdx.x] = s[1023];
}

__global__ void k_scan2() {
    __shared__ int s[1024];
    int nb = (blockIdx.x == 1) ? (NI + 1023) / 1024 : (NU + 1023) / 1024;
    int tid = threadIdx.x;
    int v = (tid < nb) ? g_bsum[blockIdx.x][tid] : 0;
    s[tid] = v;
    __syncthreads();
#pragma unroll
    for (int o = 1; o < 1024; o <<= 1) {
        int t = (tid >= o) ? s[tid - o] : 0;
        __syncthreads();
        s[tid] += t;
        __syncthreads();
    }
    if (tid < nb) g_bsum[blockIdx.x][tid] = s[tid] - v;
}

__global__ void k_scan3() {
    int* outp; int* pos; int n;
    if (blockIdx.y == 0)      { outp = g_off_f; pos = g_pos_f; n = NU; }
    else if (blockIdx.y == 1) { outp = g_off_r; pos = g_pos_r; n = NI; }
    else                      { outp = g_off_v; pos = g_pos_v; n = NU; }
    int i = blockIdx.x * blockDim.x + threadIdx.x;
    if (i < n) {
        int v = outp[i] + g_bsum[blockIdx.y][i >> 10];
        outp[i] = v;
        pos[i] = v;
    } else if (i == n) {
        outp[n] = NE;
    }
}

__global__ void k_fill3(const int* __restrict__ fs, const int* __restrict__ fd,
                        const int* __restrict__ rs, const int* __restrict__ rd,
                        const int* __restrict__ vs, const int* __restrict__ vd) {
    int e = blockIdx.x * blockDim.x + threadIdx.x;
    if (e >= NE) return;
    const int *src, *dst; const float* invs;
    int* pos; int2* eout;
    if (blockIdx.y == 0) {
        src = fs; dst = fd; invs = g_inv_fs; pos = g_pos_f; eout = g_ef;
    } else if (blockIdx.y == 1) {
        src = rs; dst = rd; invs = g_inv_rs; pos = g_pos_r; eout = g_er;
    } else {
        src = vs; dst = vd; invs = g_inv_vs; pos = g_pos_v; eout = g_ev;
    }
    int d = dst[e];
    int s = src[e];
    int p = atomicAdd(&pos[d], 1);
    eout[p] = make_int2(s, __float_as_int(invs[s]));
}

// ---------------- GEMM: C[rows](fp16) = A[rows] @ W, row-chunked ---------------

#define GEMM_SMEM ((128 * 128 + 128 * 64) * 4)  // W 64KB + At 32KB

__global__ void __launch_bounds__(256) k_gemm(const float* __restrict__ A,
                                              const float* __restrict__ W,
                                              __half* __restrict__ C,
                                              int row_base, int row_end) {
    extern __shared__ float sm[];
    float* Ws = sm;               // [128][128]
    float* At = sm + 128 * 128;   // [128 k][64 row]

    for (int i = threadIdx.x; i < 128 * 32; i += 256)
        ((float4*)Ws)[i] = ((const float4*)W)[i];

    int row0 = row_base + blockIdx.x * 64;
    for (int i = threadIdx.x; i < 64 * 32; i += 256) {
        int c = i >> 6;
        int r = i & 63;
        int row = row0 + r;
        float4 v = (row < row_end) ? ((const float4*)A)[(size_t)row * 32 + c]
                                   : make_float4(0.f, 0.f, 0.f, 0.f);
        At[(4 * c + 0) * 64 + r] = v.x;
        At[(4 * c + 1) * 64 + r] = v.y;
        At[(4 * c + 2) * 64 + r] = v.z;
        At[(4 * c + 3) * 64 + r] = v.w;
    }
    __syncthreads();

    int ty = threadIdx.x >> 5;
    int tx = threadIdx.x & 31;

    unsigned long long acc[8][2];
#pragma unroll
    for (int r = 0; r < 8; r++) { acc[r][0] = 0ull; acc[r][1] = 0ull; }

    const float* at = At + ty * 8;
#pragma unroll 8
    for (int k = 0; k < 128; k++) {
        ulonglong2 w = ((const ulonglong2*)(Ws + k * 128))[tx];
        float4 a03 = *(const float4*)(at + k * 64);
        float4 a47 = *(const float4*)(at + k * 64 + 4);
        unsigned long long p0, p1, p2, p3, p4, p5, p6, p7;
        asm("mov.b64 %0, {%1, %1};" : "=l"(p0) : "f"(a03.x));
        asm("mov.b64 %0, {%1, %1};" : "=l"(p1) : "f"(a03.y));
        asm("mov.b64 %0, {%1, %1};" : "=l"(p2) : "f"(a03.z));
        asm("mov.b64 %0, {%1, %1};" : "=l"(p3) : "f"(a03.w));
        asm("mov.b64 %0, {%1, %1};" : "=l"(p4) : "f"(a47.x));
        asm("mov.b64 %0, {%1, %1};" : "=l"(p5) : "f"(a47.y));
        asm("mov.b64 %0, {%1, %1};" : "=l"(p6) : "f"(a47.z));
        asm("mov.b64 %0, {%1, %1};" : "=l"(p7) : "f"(a47.w));
        asm("fma.rn.f32x2 %0, %1, %2, %0;" : "+l"(acc[0][0]) : "l"(p0), "l"(w.x));
        asm("fma.rn.f32x2 %0, %1, %2, %0;" : "+l"(acc[0][1]) : "l"(p0), "l"(w.y));
        asm("fma.rn.f32x2 %0, %1, %2, %0;" : "+l"(acc[1][0]) : "l"(p1), "l"(w.x));
        asm("fma.rn.f32x2 %0, %1, %2, %0;" : "+l"(acc[1][1]) : "l"(p1), "l"(w.y));
        asm("fma.rn.f32x2 %0, %1, %2, %0;" : "+l"(acc[2][0]) : "l"(p2), "l"(w.x));
        asm("fma.rn.f32x2 %0, %1, %2, %0;" : "+l"(acc[2][1]) : "l"(p2), "l"(w.y));
        asm("fma.rn.f32x2 %0, %1, %2, %0;" : "+l"(acc[3][0]) : "l"(p3), "l"(w.x));
        asm("fma.rn.f32x2 %0, %1, %2, %0;" : "+l"(acc[3][1]) : "l"(p3), "l"(w.y));
        asm("fma.rn.f32x2 %0, %1, %2, %0;" : "+l"(acc[4][0]) : "l"(p4), "l"(w.x));
        asm("fma.rn.f32x2 %0, %1, %2, %0;" : "+l"(acc[4][1]) : "l"(p4), "l"(w.y));
        asm("fma.rn.f32x2 %0, %1, %2, %0;" : "+l"(acc[5][0]) : "l"(p5), "l"(w.x));
        asm("fma.rn.f32x2 %0, %1, %2, %0;" : "+l"(acc[5][1]) : "l"(p5), "l"(w.y));
        asm("fma.rn.f32x2 %0, %1, %2, %0;" : "+l"(acc[6][0]) : "l"(p6), "l"(w.x));
        asm("fma.rn.f32x2 %0, %1, %2, %0;" : "+l"(acc[6][1]) : "l"(p6), "l"(w.y));
        asm("fma.rn.f32x2 %0, %1, %2, %0;" : "+l"(acc[7][0]) : "l"(p7), "l"(w.x));
        asm("fma.rn.f32x2 %0, %1, %2, %0;" : "+l"(acc[7][1]) : "l"(p7), "l"(w.y));
    }

#pragma unroll
    for (int r = 0; r < 8; r++) {
        int row = row0 + ty * 8 + r;
        if (row < row_end) {
            float4 o;
            asm("mov.b64 {%0, %1}, %2;" : "=f"(o.x), "=f"(o.y) : "l"(acc[r][0]));
            asm("mov.b64 {%0, %1}, %2;" : "=f"(o.z), "=f"(o.w) : "l"(acc[r][1]));
            __half2 h0 = __floats2half2_rn(o.x, o.y);
            __half2 h1 = __floats2half2_rn(o.z, o.w);
            uint2 pk = make_uint2(*(unsigned*)&h0, *(unsigned*)&h1);
            *(uint2*)(C + (size_t)row * D + tx * 4) = pk;
        }
    }
}

// ---------------- CSR gather-aggregate (fp16 gathers, fp32 accum) --------------

__device__ __forceinline__ float4 agg_list(const __half* __restrict__ h,
                                           const int2* __restrict__ eds,
                                           int j, int end, int lane) {
    float x = 0.f, y = 0.f, z = 0.f, w = 0.f;
    if (j < end && (j & 1)) {
        int2 e = __ldg(eds + j);
        float w0 = __int_as_float(e.y);
        uint2 v = __ldg((const uint2*)(h + (size_t)e.x * D) + lane);
        float2 f0 = __half22float2(*(__half2*)&v.x);
        float2 f1 = __half22float2(*(__half2*)&v.y);
        x += w0 * f0.x; y += w0 * f0.y; z += w0 * f1.x; w += w0 * f1.y;
        j++;
    }
    for (; j + 1 < end; j += 2) {
        int4 ee = __ldg((const int4*)(eds + j));
        float w0 = __int_as_float(ee.y);
        float w1 = __int_as_float(ee.w);
        uint2 v0 = __ldg((const uint2*)(h + (size_t)ee.x * D) + lane);
        uint2 v1 = __ldg((const uint2*)(h + (size_t)ee.z * D) + lane);
        float2 a0 = __half22float2(*(__half2*)&v0.x);
        float2 a1 = __half22float2(*(__half2*)&v0.y);
        float2 b0 = __half22float2(*(__half2*)&v1.x);
        float2 b1 = __half22float2(*(__half2*)&v1.y);
        x += w0 * a0.x + w1 * b0.x;
        y += w0 * a0.y + w1 * b0.y;
        z += w0 * a1.x + w1 * b1.x;
        w += w0 * a1.y + w1 * b1.y;
    }
    if (j < end) {
        int2 e = __ldg(eds + j);
        float w0 = __int_as_float(e.y);
        uint2 v = __ldg((const uint2*)(h + (size_t)e.x * D) + lane);
        float2 f0 = __half22float2(*(__half2*)&v.x);
        float2 f1 = __half22float2(*(__half2*)&v.y);
        x += w0 * f0.x; y += w0 * f0.y; z += w0 * f1.x; w += w0 * f1.y;
    }
    return make_float4(x, y, z, w);
}

template <bool RELU>
__global__ void __launch_bounds__(256) k_agg_user(
    const __half* __restrict__ hF, const __half* __restrict__ hV,
    const float* __restrict__ bF, const float* __restrict__ bV,
    float* __restrict__ outp, int node_base, int node_end) {
    int warp = node_base + ((blockIdx.x * blockDim.x + threadIdx.x) >> 5);
    if (warp >= node_end) return;
    int lane = threadIdx.x & 31;

    float4 aF = agg_list(hF, g_ef, g_off_f[warp], g_off_f[warp + 1], lane);
    float4 aV = agg_list(hV, g_ev, g_off_v[warp], g_off_v[warp + 1], lane);
    float fF = g_inv_fd[warp];
    float fV = g_inv_vd[warp];
    float4 b1 = __ldg((const float4*)bF + lane);
    float4 b2 = __ldg((const float4*)bV + lane);

    float4 o;
    o.x = 0.5f * (fF * aF.x + fV * aV.x + b1.x + b2.x);
    o.y = 0.5f * (fF * aF.y + fV * aV.y + b1.y + b2.y);
    o.z = 0.5f * (fF * aF.z + fV * aV.z + b1.z + b2.z);
    o.w = 0.5f * (fF * aF.w + fV * aV.w + b1.w + b2.w);
    if (RELU) {
        o.x = fmaxf(o.x, 0.f); o.y = fmaxf(o.y, 0.f);
        o.z = fmaxf(o.z, 0.f); o.w = fmaxf(o.w, 0.f);
    }
    ((float4*)outp)[(size_t)warp * 32 + lane] = o;
}

template <bool RELU>
__global__ void __launch_bounds__(256) k_agg_item(
    const __half* __restrict__ h, const float* __restrict__ b,
    float* __restrict__ outp) {
    int warp = (blockIdx.x * blockDim.x + threadIdx.x) >> 5;
    if (warp >= NI) return;
    int lane = threadIdx.x & 31;

    float4 a = agg_list(h, g_er, g_off_r[warp], g_off_r[warp + 1], lane);
    float f = g_inv_rd[warp];
    float4 bb = __ldg((const float4*)b + lane);

    float4 o;
    o.x = f * a.x + bb.x;
    o.y = f * a.y + bb.y;
    o.z = f * a.z + bb.z;
    o.w = f * a.w + bb.w;
    if (RELU) {
        o.x = fmaxf(o.x, 0.f); o.y = fmaxf(o.y, 0.f);
        o.z = fmaxf(o.z, 0.f); o.w = fmaxf(o.w, 0.f);
    }
    ((float4*)outp)[(size_t)warp * 32 + lane] = o;
}

// ---------------- host driver --------------------------------------------------

extern "C" void kernel_launch(void* const* d_in, const int* in_sizes, int n_in,
                              void* d_out, int out_size) {
    const float* x_user = (const float*)d_in[0];
    const float* x_item = (const float*)d_in[1];
    const int* f_src = (const int*)d_in[2];
    const int* f_dst = (const int*)d_in[3];
    const int* r_src = (const int*)d_in[4];
    const int* r_dst = (const int*)d_in[5];
    const int* v_src = (const int*)d_in[6];
    const int* v_dst = (const int*)d_in[7];

    const float *W1f, *W1r, *W1v, *W2f, *W2r, *W2v;
    const float *b1f, *b1r, *b1v, *b2f, *b2r, *b2v;
    if (in_sizes[9] == 128 * 128) {
        W1f = (const float*)d_in[8];  W1r = (const float*)d_in[9];  W1v = (const float*)d_in[10];
        W2f = (const float*)d_in[11]; W2r = (const float*)d_in[12]; W2v = (const float*)d_in[13];
        b1f = (const float*)d_in[14]; b1r = (const float*)d_in[15]; b1v = (const float*)d_in[16];
        b2f = (const float*)d_in[17]; b2r = (const float*)d_in[18]; b2v = (const float*)d_in[19];
    } else {
        W1f = (const float*)d_in[8];  b1f = (const float*)d_in[9];
        W1r = (const float*)d_in[10]; b1r = (const float*)d_in[11];
        W1v = (const float*)d_in[12]; b1v = (const float*)d_in[13];
        W2f = (const float*)d_in[14]; b2f = (const float*)d_in[15];
        W2r = (const float*)d_in[16]; b2r = (const float*)d_in[17];
        W2v = (const float*)d_in[18]; b2v = (const float*)d_in[19];
    }
    float* out = (float*)d_out;

    __half *hu1, *hu2, *hi, *hu1b, *hu2b, *hib;
    float *u, *it;
    cudaGetSymbolAddress((void**)&hu1, g_hu1);
    cudaGetSymbolAddress((void**)&hu2, g_hu2);
    cudaGetSymbolAddress((void**)&hi,  g_hi);
    cudaGetSymbolAddress((void**)&hu1b, g_hu1b);
    cudaGetSymbolAddress((void**)&hu2b, g_hu2b);
    cudaGetSymbolAddress((void**)&hib,  g_hib);
    cudaGetSymbolAddress((void**)&u,  g_u);
    cudaGetSymbolAddress((void**)&it, g_it);

    static cudaStream_t s1 = 0, s2 = 0;
    static cudaEvent_t evFork = 0, evCSR = 0, evA = 0, evB = 0, evWf = 0,
                       evItG = 0, evHu2b = 0, evEnd = 0;
    if (s1 == 0) {
        cudaStreamCreateWithFlags(&s1, cudaStreamNonBlocking);
        cudaStreamCreateWithFlags(&s2, cudaStreamNonBlocking);
        cudaEventCreateWithFlags(&evFork, cudaEventDisableTiming);
        cudaEventCreateWithFlags(&evCSR,  cudaEventDisableTiming);
        cudaEventCreateWithFlags(&evA,    cudaEventDisableTiming);
        cudaEventCreateWithFlags(&evB,    cudaEventDisableTiming);
        cudaEventCreateWithFlags(&evWf,   cudaEventDisableTiming);
        cudaEventCreateWithFlags(&evItG,  cudaEventDisableTiming);
        cudaEventCreateWithFlags(&evHu2b, cudaEventDisableTiming);
        cudaEventCreateWithFlags(&evEnd,  cudaEventDisableTiming);
    }

    const int TB = 256;
    cudaFuncSetAttribute(k_gemm, cudaFuncAttributeMaxDynamicSharedMemorySize, GEMM_SMEM);

    int gNU    = (NU + TB - 1) / TB;
    int gAggU  = (NU * 32 + TB - 1) / TB;      // full-user agg grid
    int gAggUh = (HNU * 32 + TB - 1) / TB;     // half-user agg grid
    int gAggI  = (NI * 32 + TB - 1) / TB;
    int gFull  = (NU + 63) / 64;               // full-user gemm grid
    int gHalf  = (HNU + 63) / 64;              // half-user gemm grid
    int gItem  = (NI + 63) / 64;
    int nbU = (NU + 1023) / 1024;

    dim3 gEdge3((NE + TB - 1) / TB, 3);
    dim3 gScan1(nbU, 3);
    dim3 gScan3((NU + 1 + TB - 1) / TB, 3);

    // ---- s1: CSR build, then item pipeline -----------------------------------
    cudaEventRecord(evFork, 0);
    cudaStreamWaitEvent(s1, evFork, 0);
    cudaStreamWaitEvent(s2, evFork, 0);
    k_zero_hists<<<gNU, TB, 0, s1>>>();
    k_hist3<<<gEdge3, TB, 0, s1>>>(f_src, f_dst, r_src, r_dst, v_src, v_dst);
    k_inv_all<<<gNU, TB, 0, s1>>>();
    k_scan1<<<gScan1, 1024, 0, s1>>>();
    k_scan2<<<3, 1024, 0, s1>>>();
    k_scan3<<<gScan3, TB, 0, s1>>>();
    k_fill3<<<gEdge3, TB, 0, s1>>>(f_src, f_dst, r_src, r_dst, v_src, v_dst);
    cudaEventRecord(evCSR, s1);

    // item chain on s1: hu2 GEMM -> agg_item1 -> W2v
    k_gemm<<<gFull, 256, GEMM_SMEM, s1>>>(x_user, W1r, hu2, 0, NU);
    k_agg_item<true><<<gAggI, TB, 0, s1>>>(hu2, b1r, it);
    k_gemm<<<gItem, 256, GEMM_SMEM, s1>>>(it, W2v, hib, 0, NI);
    cudaEventRecord(evItG, s1);

    // ---- s0: user-critical path with chunked agg1 ------------------------------
    k_gemm<<<gFull, 256, GEMM_SMEM>>>(x_user, W1f, hu1, 0, NU);
    k_gemm<<<gItem, 256, GEMM_SMEM>>>(x_item, W1v, hi, 0, NI);
    cudaStreamWaitEvent(0, evCSR, 0);
    k_agg_user<true><<<gAggUh, TB>>>(hu1, hi, b1f, b1v, u, 0, HNU);
    cudaEventRecord(evA, 0);
    k_agg_user<true><<<gAggUh, TB>>>(hu1, hi, b1f, b1v, u, HNU, NU);
    cudaEventRecord(evB, 0);

    // ---- s2: layer-2 user GEMMs, chunk-pipelined against agg1 ------------------
    cudaStreamWaitEvent(s2, evA, 0);
    k_gemm<<<gHalf, 256, GEMM_SMEM, s2>>>(u, W2f, hu1b, 0, HNU);     // overlaps agg chunk B
    cudaStreamWaitEvent(s2, evB, 0);
    k_gemm<<<gHalf, 256, GEMM_SMEM, s2>>>(u, W2f, hu1b, HNU, NU);
    cudaEventRecord(evWf, s2);
    k_gemm<<<gHalf, 256, GEMM_SMEM, s2>>>(u, W2r, hu2b, 0, HNU);
    k_gemm<<<gHalf, 256, GEMM_SMEM, s2>>>(u, W2r, hu2b, HNU, NU);
    cudaEventRecord(evHu2b, s2);

    // ---- final item agg on s1 (needs hu2b) --------------------------------------
    cudaStreamWaitEvent(s1, evHu2b, 0);
    k_agg_item<false><<<gAggI, TB, 0, s1>>>(hu2b, b2r, out + (size_t)NU * D);
    cudaEventRecord(evEnd, s1);

    // ---- final user agg on s0 (needs full hu1b + hib) ----------------------------
    cudaStreamWaitEvent(0, evWf, 0);
    cudaStreamWaitEvent(0, evItG, 0);
    k_agg_user<false><<<gAggU, TB>>>(hu1b, hib, b2f, b2v, out, 0, NU);
    cudaStreamWaitEvent(0, evEnd, 0);  // join
}

// round 10
// speedup vs baseline: 1.4871x; 1.4871x over previous
#include <cuda_runtime.h>
#include <cuda_fp16.h>

#define NU 100000
#define NI 50000
#define NE 1600000
#define D  128

// ---------------- scratch (device globals) ----------------------------------
__device__ int g_h_fs[NU];
__device__ int g_h_fd[NU];
__device__ int g_h_rs[NU];
__device__ int g_h_rd[NI];
__device__ int g_h_vs[NI];
__device__ int g_h_vd[NU];

__device__ float g_inv_fs[NU];
__device__ float g_inv_fd[NU];
__device__ float g_inv_rs[NU];
__device__ float g_inv_rd[NI];
__device__ float g_inv_vs[NI];
__device__ float g_inv_vd[NU];

__device__ int   g_off_f[NU + 1];
__device__ int   g_off_r[NI + 1];
__device__ int   g_off_v[NU + 1];
__device__ int   g_pos_f[NU];
__device__ int   g_pos_r[NI];
__device__ int   g_pos_v[NU];
__device__ int2  g_ef[NE];   // packed {src, w_bits} sorted by dst
__device__ int2  g_er[NE];
__device__ int2  g_ev[NE];
__device__ int   g_bsum[3][1024];

// h buffers in fp16 (gather hot path); u/it in fp32 (GEMM inputs)
__device__ __half g_hu1[(size_t)NU * D];
__device__ __half g_hu2[(size_t)NU * D];
__device__ __half g_hi [(size_t)NI * D];
__device__ __half g_hu1b[(size_t)NU * D];
__device__ __half g_hu2b[(size_t)NU * D];
__device__ __half g_hib [(size_t)NI * D];
__device__ float  g_u  [(size_t)NU * D];
__device__ float  g_it [(size_t)NI * D];

// ---------------- setup kernels ----------------------------------------------

__global__ void k_zero_hists() {
    int i = blockIdx.x * blockDim.x + threadIdx.x;
    if (i < NU) { g_h_fs[i] = 0; g_h_fd[i] = 0; g_h_rs[i] = 0; g_h_vd[i] = 0; }
    if (i < NI) { g_h_rd[i] = 0; g_h_vs[i] = 0; }
}

__global__ void k_hist3(const int* __restrict__ fs, const int* __restrict__ fd,
                        const int* __restrict__ rs, const int* __restrict__ rd,
                        const int* __restrict__ vs, const int* __restrict__ vd) {
    int e = blockIdx.x * blockDim.x + threadIdx.x;
    if (e >= NE) return;
    if (blockIdx.y == 0) {
        atomicAdd(&g_h_fs[fs[e]], 1);
        atomicAdd(&g_h_fd[fd[e]], 1);
    } else if (blockIdx.y == 1) {
        atomicAdd(&g_h_rs[rs[e]], 1);
        atomicAdd(&g_h_rd[rd[e]], 1);
    } else {
        atomicAdd(&g_h_vs[vs[e]], 1);
        atomicAdd(&g_h_vd[vd[e]], 1);
    }
}

__device__ __forceinline__ float invsq(int x) {
    return x > 0 ? rsqrtf((float)x) : 0.f;
}

__global__ void k_inv_all() {
    int i = blockIdx.x * blockDim.x + threadIdx.x;
    if (i < NU) {
        g_inv_fs[i] = invsq(g_h_fs[i]);
        g_inv_fd[i] = invsq(g_h_fd[i]);
        g_inv_rs[i] = invsq(g_h_rs[i]);
        g_inv_vd[i] = invsq(g_h_vd[i]);
    }
    if (i < NI) {
        g_inv_rd[i] = invsq(g_h_rd[i]);
        g_inv_vs[i] = invsq(g_h_vs[i]);
    }
}

// ---------------- exclusive scan (3 arrays per launch via blockIdx.y) ---------

__global__ void k_scan1() {
    __shared__ int s[1024];
    const int* in; int* outp; int n;
    if (blockIdx.y == 0)      { in = g_h_fd; outp = g_off_f; n = NU; }
    else if (blockIdx.y == 1) { in = g_h_rd; outp = g_off_r; n = NI; }
    else                      { in = g_h_vd; outp = g_off_v; n = NU; }
    int tid = threadIdx.x;
    int i = blockIdx.x * 1024 + tid;
    int v = (i < n) ? in[i] : 0;
    s[tid] = v;
    __syncthreads();
#pragma unroll
    for (int o = 1; o < 1024; o <<= 1) {
        int t = (tid >= o) ? s[tid - o] : 0;
        __syncthreads();
        s[tid] += t;
        __syncthreads();
    }
    if (i < n) outp[i] = s[tid] - v;
    if (tid == 1023) g_bsum[blockIdx.y][blockIdx.x] = s[1023];
}

__global__ void k_scan2() {
    __shared__ int s[1024];
    int nb = (blockIdx.x == 1) ? (NI + 1023) / 1024 : (NU + 1023) / 1024;
    int tid = threadIdx.x;
    int v = (tid < nb) ? g_bsum[blockIdx.x][tid] : 0;
    s[tid] = v;
    __syncthreads();
#pragma unroll
    for (int o = 1; o < 1024; o <<= 1) {
        int t = (tid >= o) ? s[tid - o] : 0;
        __syncthreads();
        s[tid] += t;
        __syncthreads();
    }
    if (tid < nb) g_bsum[blockIdx.x][tid] = s[tid] - v;
}

__global__ void k_scan3() {
    int* outp; int* pos; int n;
    if (blockIdx.y == 0)      { outp = g_off_f; pos = g_pos_f; n = NU; }
    else if (blockIdx.y == 1) { outp = g_off_r; pos = g_pos_r; n = NI; }
    else                      { outp = g_off_v; pos = g_pos_v; n = NU; }
    int i = blockIdx.x * blockDim.x + threadIdx.x;
    if (i < n) {
        int v = outp[i] + g_bsum[blockIdx.y][i >> 10];
        outp[i] = v;
        pos[i] = v;
    } else if (i == n) {
        outp[n] = NE;
    }
}

__global__ void k_fill3(const int* __restrict__ fs, const int* __restrict__ fd,
                        const int* __restrict__ rs, const int* __restrict__ rd,
                        const int* __restrict__ vs, const int* __restrict__ vd) {
    int e = blockIdx.x * blockDim.x + threadIdx.x;
    if (e >= NE) return;
    const int *src, *dst; const float* invs;
    int* pos; int2* eout;
    if (blockIdx.y == 0) {
        src = fs; dst = fd; invs = g_inv_fs; pos = g_pos_f; eout = g_ef;
    } else if (blockIdx.y == 1) {
        src = rs; dst = rd; invs = g_inv_rs; pos = g_pos_r; eout = g_er;
    } else {
        src = vs; dst = vd; invs = g_inv_vs; pos = g_pos_v; eout = g_ev;
    }
    int d = dst[e];
    int s = src[e];
    int p = atomicAdd(&pos[d], 1);
    eout[p] = make_int2(s, __float_as_int(invs[s]));
}

// ---------------- GEMM: C[n,128](fp16) = A[n,128](fp32) @ W[128,128](fp32) ----
// 64 rows/block, 256 threads, 96KB smem (2 blocks/SM). A staged TRANSPOSED.

#define GEMM_SMEM ((128 * 128 + 128 * 64) * 4)  // W 64KB + At 32KB

__global__ void __launch_bounds__(256) k_gemm(const float* __restrict__ A,
                                              const float* __restrict__ W,
                                              __half* __restrict__ C, int n) {
    extern __shared__ float sm[];
    float* Ws = sm;               // [128][128]
    float* At = sm + 128 * 128;   // [128 k][64 row]

    for (int i = threadIdx.x; i < 128 * 32; i += 256)
        ((float4*)Ws)[i] = ((const float4*)W)[i];

    int row0 = blockIdx.x * 64;
    for (int i = threadIdx.x; i < 64 * 32; i += 256) {
        int c = i >> 6;
        int r = i & 63;
        int row = row0 + r;
        float4 v = (row < n) ? ((const float4*)A)[(size_t)row * 32 + c]
                             : make_float4(0.f, 0.f, 0.f, 0.f);
        At[(4 * c + 0) * 64 + r] = v.x;
        At[(4 * c + 1) * 64 + r] = v.y;
        At[(4 * c + 2) * 64 + r] = v.z;
        At[(4 * c + 3) * 64 + r] = v.w;
    }
    __syncthreads();

    int ty = threadIdx.x >> 5;
    int tx = threadIdx.x & 31;

    unsigned long long acc[8][2];
#pragma unroll
    for (int r = 0; r < 8; r++) { acc[r][0] = 0ull; acc[r][1] = 0ull; }

    const float* at = At + ty * 8;
#pragma unroll 8
    for (int k = 0; k < 128; k++) {
        ulonglong2 w = ((const ulonglong2*)(Ws + k * 128))[tx];
        float4 a03 = *(const float4*)(at + k * 64);
        float4 a47 = *(const float4*)(at + k * 64 + 4);
        unsigned long long p0, p1, p2, p3, p4, p5, p6, p7;
        asm("mov.b64 %0, {%1, %1};" : "=l"(p0) : "f"(a03.x));
        asm("mov.b64 %0, {%1, %1};" : "=l"(p1) : "f"(a03.y));
        asm("mov.b64 %0, {%1, %1};" : "=l"(p2) : "f"(a03.z));
        asm("mov.b64 %0, {%1, %1};" : "=l"(p3) : "f"(a03.w));
        asm("mov.b64 %0, {%1, %1};" : "=l"(p4) : "f"(a47.x));
        asm("mov.b64 %0, {%1, %1};" : "=l"(p5) : "f"(a47.y));
        asm("mov.b64 %0, {%1, %1};" : "=l"(p6) : "f"(a47.z));
        asm("mov.b64 %0, {%1, %1};" : "=l"(p7) : "f"(a47.w));
        asm("fma.rn.f32x2 %0, %1, %2, %0;" : "+l"(acc[0][0]) : "l"(p0), "l"(w.x));
        asm("fma.rn.f32x2 %0, %1, %2, %0;" : "+l"(acc[0][1]) : "l"(p0), "l"(w.y));
        asm("fma.rn.f32x2 %0, %1, %2, %0;" : "+l"(acc[1][0]) : "l"(p1), "l"(w.x));
        asm("fma.rn.f32x2 %0, %1, %2, %0;" : "+l"(acc[1][1]) : "l"(p1), "l"(w.y));
        asm("fma.rn.f32x2 %0, %1, %2, %0;" : "+l"(acc[2][0]) : "l"(p2), "l"(w.x));
        asm("fma.rn.f32x2 %0, %1, %2, %0;" : "+l"(acc[2][1]) : "l"(p2), "l"(w.y));
        asm("fma.rn.f32x2 %0, %1, %2, %0;" : "+l"(acc[3][0]) : "l"(p3), "l"(w.x));
        asm("fma.rn.f32x2 %0, %1, %2, %0;" : "+l"(acc[3][1]) : "l"(p3), "l"(w.y));
        asm("fma.rn.f32x2 %0, %1, %2, %0;" : "+l"(acc[4][0]) : "l"(p4), "l"(w.x));
        asm("fma.rn.f32x2 %0, %1, %2, %0;" : "+l"(acc[4][1]) : "l"(p4), "l"(w.y));
        asm("fma.rn.f32x2 %0, %1, %2, %0;" : "+l"(acc[5][0]) : "l"(p5), "l"(w.x));
        asm("fma.rn.f32x2 %0, %1, %2, %0;" : "+l"(acc[5][1]) : "l"(p5), "l"(w.y));
        asm("fma.rn.f32x2 %0, %1, %2, %0;" : "+l"(acc[6][0]) : "l"(p6), "l"(w.x));
        asm("fma.rn.f32x2 %0, %1, %2, %0;" : "+l"(acc[6][1]) : "l"(p6), "l"(w.y));
        asm("fma.rn.f32x2 %0, %1, %2, %0;" : "+l"(acc[7][0]) : "l"(p7), "l"(w.x));
        asm("fma.rn.f32x2 %0, %1, %2, %0;" : "+l"(acc[7][1]) : "l"(p7), "l"(w.y));
    }

#pragma unroll
    for (int r = 0; r < 8; r++) {
        int row = row0 + ty * 8 + r;
        if (row < n) {
            float4 o;
            asm("mov.b64 {%0, %1}, %2;" : "=f"(o.x), "=f"(o.y) : "l"(acc[r][0]));
            asm("mov.b64 {%0, %1}, %2;" : "=f"(o.z), "=f"(o.w) : "l"(acc[r][1]));
            __half2 h0 = __floats2half2_rn(o.x, o.y);
            __half2 h1 = __floats2half2_rn(o.z, o.w);
            uint2 pk = make_uint2(*(unsigned*)&h0, *(unsigned*)&h1);
            *(uint2*)(C + (size_t)row * D + tx * 4) = pk;
        }
    }
}

// ---------------- CSR gather-aggregate (fp16 gathers, fp32 accum) --------------

__device__ __forceinline__ float4 agg_list(const __half* __restrict__ h,
                                           const int2* __restrict__ eds,
                                           int j, int end, int lane) {
    float x = 0.f, y = 0.f, z = 0.f, w = 0.f;
    if (j < end && (j & 1)) {
        int2 e = __ldg(eds + j);
        float w0 = __int_as_float(e.y);
        uint2 v = __ldg((const uint2*)(h + (size_t)e.x * D) + lane);
        float2 f0 = __half22float2(*(__half2*)&v.x);
        float2 f1 = __half22float2(*(__half2*)&v.y);
        x += w0 * f0.x; y += w0 * f0.y; z += w0 * f1.x; w += w0 * f1.y;
        j++;
    }
    for (; j + 1 < end; j += 2) {
        int4 ee = __ldg((const int4*)(eds + j));
        float w0 = __int_as_float(ee.y);
        float w1 = __int_as_float(ee.w);
        uint2 v0 = __ldg((const uint2*)(h + (size_t)ee.x * D) + lane);
        uint2 v1 = __ldg((const uint2*)(h + (size_t)ee.z * D) + lane);
        float2 a0 = __half22float2(*(__half2*)&v0.x);
        float2 a1 = __half22float2(*(__half2*)&v0.y);
        float2 b0 = __half22float2(*(__half2*)&v1.x);
        float2 b1 = __half22float2(*(__half2*)&v1.y);
        x += w0 * a0.x + w1 * b0.x;
        y += w0 * a0.y + w1 * b0.y;
        z += w0 * a1.x + w1 * b1.x;
        w += w0 * a1.y + w1 * b1.y;
    }
    if (j < end) {
        int2 e = __ldg(eds + j);
        float w0 = __int_as_float(e.y);
        uint2 v = __ldg((const uint2*)(h + (size_t)e.x * D) + lane);
        float2 f0 = __half22float2(*(__half2*)&v.x);
        float2 f1 = __half22float2(*(__half2*)&v.y);
        x += w0 * f0.x; y += w0 * f0.y; z += w0 * f1.x; w += w0 * f1.y;
    }
    return make_float4(x, y, z, w);
}

template <bool RELU>
__global__ void __launch_bounds__(256) k_agg_user(
    const __half* __restrict__ hF, const __half* __restrict__ hV,
    const float* __restrict__ bF, const float* __restrict__ bV,
    float* __restrict__ outp) {
    int warp = (blockIdx.x * blockDim.x + threadIdx.x) >> 5;
    if (warp >= NU) return;
    int lane = threadIdx.x & 31;

    float4 aF = agg_list(hF, g_ef, g_off_f[warp], g_off_f[warp + 1], lane);
    float4 aV = agg_list(hV, g_ev, g_off_v[warp], g_off_v[warp + 1], lane);
    float fF = g_inv_fd[warp];
    float fV = g_inv_vd[warp];
    float4 b1 = __ldg((const float4*)bF + lane);
    float4 b2 = __ldg((const float4*)bV + lane);

    float4 o;
    o.x = 0.5f * (fF * aF.x + fV * aV.x + b1.x + b2.x);
    o.y = 0.5f * (fF * aF.y + fV * aV.y + b1.y + b2.y);
    o.z = 0.5f * (fF * aF.z + fV * aV.z + b1.z + b2.z);
    o.w = 0.5f * (fF * aF.w + fV * aV.w + b1.w + b2.w);
    if (RELU) {
        o.x = fmaxf(o.x, 0.f); o.y = fmaxf(o.y, 0.f);
        o.z = fmaxf(o.z, 0.f); o.w = fmaxf(o.w, 0.f);
    }
    ((float4*)outp)[(size_t)warp * 32 + lane] = o;
}

template <bool RELU>
__global__ void __launch_bounds__(256) k_agg_item(
    const __half* __restrict__ h, const float* __restrict__ b,
    float* __restrict__ outp) {
    int warp = (blockIdx.x * blockDim.x + threadIdx.x) >> 5;
    if (warp >= NI) return;
    int lane = threadIdx.x & 31;

    float4 a = agg_list(h, g_er, g_off_r[warp], g_off_r[warp + 1], lane);
    float f = g_inv_rd[warp];
    float4 bb = __ldg((const float4*)b + lane);

    float4 o;
    o.x = f * a.x + bb.x;
    o.y = f * a.y + bb.y;
    o.z = f * a.z + bb.z;
    o.w = f * a.w + bb.w;
    if (RELU) {
        o.x = fmaxf(o.x, 0.f); o.y = fmaxf(o.y, 0.f);
        o.z = fmaxf(o.z, 0.f); o.w = fmaxf(o.w, 0.f);
    }
    ((float4*)outp)[(size_t)warp * 32 + lane] = o;
}

// ---------------- host driver --------------------------------------------------

extern "C" void kernel_launch(void* const* d_in, const int* in_sizes, int n_in,
                              void* d_out, int out_size) {
    const float* x_user = (const float*)d_in[0];
    const float* x_item = (const float*)d_in[1];
    const int* f_src = (const int*)d_in[2];
    const int* f_dst = (const int*)d_in[3];
    const int* r_src = (const int*)d_in[4];
    const int* r_dst = (const int*)d_in[5];
    const int* v_src = (const int*)d_in[6];
    const int* v_dst = (const int*)d_in[7];

    const float *W1f, *W1r, *W1v, *W2f, *W2r, *W2v;
    const float *b1f, *b1r, *b1v, *b2f, *b2r, *b2v;
    if (in_sizes[9] == 128 * 128) {
        W1f = (const float*)d_in[8];  W1r = (const float*)d_in[9];  W1v = (const float*)d_in[10];
        W2f = (const float*)d_in[11]; W2r = (const float*)d_in[12]; W2v = (const float*)d_in[13];
        b1f = (const float*)d_in[14]; b1r = (const float*)d_in[15]; b1v = (const float*)d_in[16];
        b2f = (const float*)d_in[17]; b2r = (const float*)d_in[18]; b2v = (const float*)d_in[19];
    } else {
        W1f = (const float*)d_in[8];  b1f = (const float*)d_in[9];
        W1r = (const float*)d_in[10]; b1r = (const float*)d_in[11];
        W1v = (const float*)d_in[12]; b1v = (const float*)d_in[13];
        W2f = (const float*)d_in[14]; b2f = (const float*)d_in[15];
        W2r = (const float*)d_in[16]; b2r = (const float*)d_in[17];
        W2v = (const float*)d_in[18]; b2v = (const float*)d_in[19];
    }
    float* out = (float*)d_out;

    __half *hu1, *hu2, *hi, *hu1b, *hu2b, *hib;
    float *u, *it;
    cudaGetSymbolAddress((void**)&hu1, g_hu1);
    cudaGetSymbolAddress((void**)&hu2, g_hu2);
    cudaGetSymbolAddress((void**)&hi,  g_hi);
    cudaGetSymbolAddress((void**)&hu1b, g_hu1b);
    cudaGetSymbolAddress((void**)&hu2b, g_hu2b);
    cudaGetSymbolAddress((void**)&hib,  g_hib);
    cudaGetSymbolAddress((void**)&u,  g_u);
    cudaGetSymbolAddress((void**)&it, g_it);

    static cudaStream_t s1 = 0, s2 = 0;
    static cudaEvent_t evFork = 0, evCSR = 0, evHu2 = 0, evU = 0, evItG = 0,
                       evHu2b = 0, evEnd = 0;
    if (s1 == 0) {
        cudaStreamCreateWithFlags(&s1, cudaStreamNonBlocking);
        cudaStreamCreateWithFlags(&s2, cudaStreamNonBlocking);
        cudaEventCreateWithFlags(&evFork, cudaEventDisableTiming);
        cudaEventCreateWithFlags(&evCSR,  cudaEventDisableTiming);
        cudaEventCreateWithFlags(&evHu2,  cudaEventDisableTiming);
        cudaEventCreateWithFlags(&evU,    cudaEventDisableTiming);
        cudaEventCreateWithFlags(&evItG,  cudaEventDisableTiming);
        cudaEventCreateWithFlags(&evHu2b, cudaEventDisableTiming);
        cudaEventCreateWithFlags(&evEnd,  cudaEventDisableTiming);
    }

    const int TB = 256;
    cudaFuncSetAttribute(k_gemm, cudaFuncAttributeMaxDynamicSharedMemorySize, GEMM_SMEM);

    int gNU   = (NU + TB - 1) / TB;
    int gAggU = (NU * 32 + TB - 1) / TB;
    int gAggI = (NI * 32 + TB - 1) / TB;
    int nbU = (NU + 1023) / 1024;

    dim3 gEdge3((NE + TB - 1) / TB, 3);
    dim3 gScan1(nbU, 3);
    dim3 gScan3((NU + 1 + TB - 1) / TB, 3);

    // ---- fork: CSR build on s1 (DRAM/atomic-bound) --------------------------
    cudaEventRecord(evFork, 0);
    cudaStreamWaitEvent(s1, evFork, 0);
    cudaStreamWaitEvent(s2, evFork, 0);
    k_zero_hists<<<gNU, TB, 0, s1>>>();
    k_hist3<<<gEdge3, TB, 0, s1>>>(f_src, f_dst, r_src, r_dst, v_src, v_dst);
    k_inv_all<<<gNU, TB, 0, s1>>>();
    k_scan1<<<gScan1, 1024, 0, s1>>>();
    k_scan2<<<3, 1024, 0, s1>>>();
    k_scan3<<<gScan3, TB, 0, s1>>>();
    k_fill3<<<gEdge3, TB, 0, s1>>>(f_src, f_dst, r_src, r_dst, v_src, v_dst);
    cudaEventRecord(evCSR, s1);

    // ---- legacy: layer-1 GEMMs (fma-bound, overlaps CSR) ---------------------
    k_gemm<<<(NU + 63) / 64, 256, GEMM_SMEM>>>(x_user, W1r, hu2, NU);
    cudaEventRecord(evHu2, 0);
    k_gemm<<<(NU + 63) / 64, 256, GEMM_SMEM>>>(x_user, W1f, hu1, NU);
    k_gemm<<<(NI + 63) / 64, 256, GEMM_SMEM>>>(x_item, W1v, hi,  NI);

    // ---- item pipeline on s1: agg_item1 -> it@W2v ----------------------------
    cudaStreamWaitEvent(s1, evHu2, 0);
    k_agg_item<true><<<gAggI, TB, 0, s1>>>(hu2, b1r, it);
    k_gemm<<<(NI + 63) / 64, 256, GEMM_SMEM, s1>>>(it, W2v, hib, NI);
    cudaEventRecord(evItG, s1);

    // ---- user pipeline on legacy: agg1 -> W2f only ----------------------------
    cudaStreamWaitEvent(0, evCSR, 0);
    k_agg_user<true><<<gAggU, TB>>>(hu1, hi, b1f, b1v, u);
    cudaEventRecord(evU, 0);
    k_gemm<<<(NU + 63) / 64, 256, GEMM_SMEM>>>(u, W2f, hu1b, NU);

    // ---- W2r on s2 (off s0's critical path; overlaps agg_user2) ---------------
    cudaStreamWaitEvent(s2, evU, 0);
    k_gemm<<<(NU + 63) / 64, 256, GEMM_SMEM, s2>>>(u, W2r, hu2b, NU);
    cudaEventRecord(evHu2b, s2);

    // ---- final item agg on s1 (needs hu2b from s2) -----------------------------
    cudaStreamWaitEvent(s1, evHu2b, 0);
    k_agg_item<false><<<gAggI, TB, 0, s1>>>(hu2b, b2r, out + (size_t)NU * D);
    cudaEventRecord(evEnd, s1);

    // ---- final user agg on s0: needs hu1b (in-order) + hib (evItG) -------------
    cudaStreamWaitEvent(0, evItG, 0);
    k_agg_user<false><<<gAggU, TB>>>(hu1b, hib, b2f, b2v, out);
    cudaStreamWaitEvent(0, evEnd, 0);  // join
}

// round 11
// speedup vs baseline: 1.5501x; 1.0423x over previous
#include <cuda_runtime.h>
#include <cuda_fp16.h>

#define NU 100000
#define NI 50000
#define NE 1600000
#define D  128

// ---------------- scratch (device globals) ----------------------------------
__device__ int g_h_fs[NU];
__device__ int g_h_fd[NU];
__device__ int g_h_rs[NU];
__device__ int g_h_rd[NI];
__device__ int g_h_vs[NI];
__device__ int g_h_vd[NU];

__device__ float g_inv_fs[NU];
__device__ float g_inv_fd[NU];
__device__ float g_inv_rs[NU];
__device__ float g_inv_rd[NI];
__device__ float g_inv_vs[NI];
__device__ float g_inv_vd[NU];

__device__ int   g_off_f[NU + 1];
__device__ int   g_off_r[NI + 1];
__device__ int   g_off_v[NU + 1];
__device__ int   g_pos_f[NU];
__device__ int   g_pos_r[NI];
__device__ int   g_pos_v[NU];
__device__ int2  g_ef[NE];   // packed {src, w_bits} sorted by dst
__device__ int2  g_er[NE];
__device__ int2  g_ev[NE];
__device__ int   g_bsum[3][1024];

__device__ __half g_hu1[(size_t)NU * D];
__device__ __half g_hu2[(size_t)NU * D];
__device__ __half g_hi [(size_t)NI * D];
__device__ __half g_hu1b[(size_t)NU * D];
__device__ __half g_hu2b[(size_t)NU * D];
__device__ __half g_hib [(size_t)NI * D];
__device__ float  g_u  [(size_t)NU * D];
__device__ float  g_it [(size_t)NI * D];

// ---------------- setup kernels ----------------------------------------------

__global__ void k_zero_hists() {
    int i = blockIdx.x * blockDim.x + threadIdx.x;
    if (i < NU) { g_h_fs[i] = 0; g_h_fd[i] = 0; g_h_rs[i] = 0; g_h_vd[i] = 0; }
    if (i < NI) { g_h_rd[i] = 0; g_h_vs[i] = 0; }
}

__global__ void k_hist3(const int* __restrict__ fs, const int* __restrict__ fd,
                        const int* __restrict__ rs, const int* __restrict__ rd,
                        const int* __restrict__ vs, const int* __restrict__ vd) {
    int e = blockIdx.x * blockDim.x + threadIdx.x;
    if (e >= NE) return;
    if (blockIdx.y == 0) {
        atomicAdd(&g_h_fs[fs[e]], 1);
        atomicAdd(&g_h_fd[fd[e]], 1);
    } else if (blockIdx.y == 1) {
        atomicAdd(&g_h_rs[rs[e]], 1);
        atomicAdd(&g_h_rd[rd[e]], 1);
    } else {
        atomicAdd(&g_h_vs[vs[e]], 1);
        atomicAdd(&g_h_vd[vd[e]], 1);
    }
}

__device__ __forceinline__ float invsq(int x) {
    return x > 0 ? rsqrtf((float)x) : 0.f;
}

__global__ void k_inv_all() {
    int i = blockIdx.x * blockDim.x + threadIdx.x;
    if (i < NU) {
        g_inv_fs[i] = invsq(g_h_fs[i]);
        g_inv_fd[i] = invsq(g_h_fd[i]);
        g_inv_rs[i] = invsq(g_h_rs[i]);
        g_inv_vd[i] = invsq(g_h_vd[i]);
    }
    if (i < NI) {
        g_inv_rd[i] = invsq(g_h_rd[i]);
        g_inv_vs[i] = invsq(g_h_vs[i]);
    }
}

// ---------------- exclusive scan (3 arrays per launch via blockIdx.y) ---------

__global__ void k_scan1() {
    __shared__ int s[1024];
    const int* in; int* outp; int n;
    if (blockIdx.y == 0)      { in = g_h_fd; outp = g_off_f; n = NU; }
    else if (blockIdx.y == 1) { in = g_h_rd; outp = g_off_r; n = NI; }
    else                      { in = g_h_vd; outp = g_off_v; n = NU; }
    int tid = threadIdx.x;
    int i = blockIdx.x * 1024 + tid;
    int v = (i < n) ? in[i] : 0;
    s[tid] = v;
    __syncthreads();
#pragma unroll
    for (int o = 1; o < 1024; o <<= 1) {
        int t = (tid >= o) ? s[tid - o] : 0;
        __syncthreads();
        s[tid] += t;
        __syncthreads();
    }
    if (i < n) outp[i] = s[tid] - v;
    if (tid == 1023) g_bsum[blockIdx.y][blockIdx.x] = s[1023];
}

__global__ void k_scan2() {
    __shared__ int s[1024];
    int nb = (blockIdx.x == 1) ? (NI + 1023) / 1024 : (NU + 1023) / 1024;
    int tid = threadIdx.x;
    int v = (tid < nb) ? g_bsum[blockIdx.x][tid] : 0;
    s[tid] = v;
    __syncthreads();
#pragma unroll
    for (int o = 1; o < 1024; o <<= 1) {
        int t = (tid >= o) ? s[tid - o] : 0;
        __syncthreads();
        s[tid] += t;
        __syncthreads();
    }
    if (tid < nb) g_bsum[blockIdx.x][tid] = s[tid] - v;
}

__global__ void k_scan3() {
    int* outp; int* pos; int n;
    if (blockIdx.y == 0)      { outp = g_off_f; pos = g_pos_f; n = NU; }
    else if (blockIdx.y == 1) { outp = g_off_r; pos = g_pos_r; n = NI; }
    else                      { outp = g_off_v; pos = g_pos_v; n = NU; }
    int i = blockIdx.x * blockDim.x + threadIdx.x;
    if (i < n) {
        int v = outp[i] + g_bsum[blockIdx.y][i >> 10];
        outp[i] = v;
        pos[i] = v;
    } else if (i == n) {
        outp[n] = NE;
    }
}

__global__ void k_fill3(const int* __restrict__ fs, const int* __restrict__ fd,
                        const int* __restrict__ rs, const int* __restrict__ rd,
                        const int* __restrict__ vs, const int* __restrict__ vd) {
    int e = blockIdx.x * blockDim.x + threadIdx.x;
    if (e >= NE) return;
    const int *src, *dst; const float* invs;
    int* pos; int2* eout;
    if (blockIdx.y == 0) {
        src = fs; dst = fd; invs = g_inv_fs; pos = g_pos_f; eout = g_ef;
    } else if (blockIdx.y == 1) {
        src = rs; dst = rd; invs = g_inv_rs; pos = g_pos_r; eout = g_er;
    } else {
        src = vs; dst = vd; invs = g_inv_vs; pos = g_pos_v; eout = g_ev;
    }
    int d = dst[e];
    int s = src[e];
    int p = atomicAdd(&pos[d], 1);
    eout[p] = make_int2(s, __float_as_int(invs[s]));
}

// ---------------- GEMM: C[n,128](fp16) = A[n,128](fp32) @ W[128,128](fp32) ----

#define GEMM_SMEM ((128 * 128 + 128 * 64) * 4)  // W 64KB + At 32KB

__global__ void __launch_bounds__(256) k_gemm(const float* __restrict__ A,
                                              const float* __restrict__ W,
                                              __half* __restrict__ C, int n) {
    extern __shared__ float sm[];
    float* Ws = sm;               // [128][128]
    float* At = sm + 128 * 128;   // [128 k][64 row]

    for (int i = threadIdx.x; i < 128 * 32; i += 256)
        ((float4*)Ws)[i] = ((const float4*)W)[i];

    int row0 = blockIdx.x * 64;
    for (int i = threadIdx.x; i < 64 * 32; i += 256) {
        int c = i >> 6;
        int r = i & 63;
        int row = row0 + r;
        float4 v = (row < n) ? ((const float4*)A)[(size_t)row * 32 + c]
                             : make_float4(0.f, 0.f, 0.f, 0.f);
        At[(4 * c + 0) * 64 + r] = v.x;
        At[(4 * c + 1) * 64 + r] = v.y;
        At[(4 * c + 2) * 64 + r] = v.z;
        At[(4 * c + 3) * 64 + r] = v.w;
    }
    __syncthreads();

    int ty = threadIdx.x >> 5;
    int tx = threadIdx.x & 31;

    unsigned long long acc[8][2];
#pragma unroll
    for (int r = 0; r < 8; r++) { acc[r][0] = 0ull; acc[r][1] = 0ull; }

    const float* at = At + ty * 8;
#pragma unroll 8
    for (int k = 0; k < 128; k++) {
        ulonglong2 w = ((const ulonglong2*)(Ws + k * 128))[tx];
        float4 a03 = *(const float4*)(at + k * 64);
        float4 a47 = *(const float4*)(at + k * 64 + 4);
        unsigned long long p0, p1, p2, p3, p4, p5, p6, p7;
        asm("mov.b64 %0, {%1, %1};" : "=l"(p0) : "f"(a03.x));
        asm("mov.b64 %0, {%1, %1};" : "=l"(p1) : "f"(a03.y));
        asm("mov.b64 %0, {%1, %1};" : "=l"(p2) : "f"(a03.z));
        asm("mov.b64 %0, {%1, %1};" : "=l"(p3) : "f"(a03.w));
        asm("mov.b64 %0, {%1, %1};" : "=l"(p4) : "f"(a47.x));
        asm("mov.b64 %0, {%1, %1};" : "=l"(p5) : "f"(a47.y));
        asm("mov.b64 %0, {%1, %1};" : "=l"(p6) : "f"(a47.z));
        asm("mov.b64 %0, {%1, %1};" : "=l"(p7) : "f"(a47.w));
        asm("fma.rn.f32x2 %0, %1, %2, %0;" : "+l"(acc[0][0]) : "l"(p0), "l"(w.x));
        asm("fma.rn.f32x2 %0, %1, %2, %0;" : "+l"(acc[0][1]) : "l"(p0), "l"(w.y));
        asm("fma.rn.f32x2 %0, %1, %2, %0;" : "+l"(acc[1][0]) : "l"(p1), "l"(w.x));
        asm("fma.rn.f32x2 %0, %1, %2, %0;" : "+l"(acc[1][1]) : "l"(p1), "l"(w.y));
        asm("fma.rn.f32x2 %0, %1, %2, %0;" : "+l"(acc[2][0]) : "l"(p2), "l"(w.x));
        asm("fma.rn.f32x2 %0, %1, %2, %0;" : "+l"(acc[2][1]) : "l"(p2), "l"(w.y));
        asm("fma.rn.f32x2 %0, %1, %2, %0;" : "+l"(acc[3][0]) : "l"(p3), "l"(w.x));
        asm("fma.rn.f32x2 %0, %1, %2, %0;" : "+l"(acc[3][1]) : "l"(p3), "l"(w.y));
        asm("fma.rn.f32x2 %0, %1, %2, %0;" : "+l"(acc[4][0]) : "l"(p4), "l"(w.x));
        asm("fma.rn.f32x2 %0, %1, %2, %0;" : "+l"(acc[4][1]) : "l"(p4), "l"(w.y));
        asm("fma.rn.f32x2 %0, %1, %2, %0;" : "+l"(acc[5][0]) : "l"(p5), "l"(w.x));
        asm("fma.rn.f32x2 %0, %1, %2, %0;" : "+l"(acc[5][1]) : "l"(p5), "l"(w.y));
        asm("fma.rn.f32x2 %0, %1, %2, %0;" : "+l"(acc[6][0]) : "l"(p6), "l"(w.x));
        asm("fma.rn.f32x2 %0, %1, %2, %0;" : "+l"(acc[6][1]) : "l"(p6), "l"(w.y));
        asm("fma.rn.f32x2 %0, %1, %2, %0;" : "+l"(acc[7][0]) : "l"(p7), "l"(w.x));
        asm("fma.rn.f32x2 %0, %1, %2, %0;" : "+l"(acc[7][1]) : "l"(p7), "l"(w.y));
    }

#pragma unroll
    for (int r = 0; r < 8; r++) {
        int row = row0 + ty * 8 + r;
        if (row < n) {
            float4 o;
            asm("mov.b64 {%0, %1}, %2;" : "=f"(o.x), "=f"(o.y) : "l"(acc[r][0]));
            asm("mov.b64 {%0, %1}, %2;" : "=f"(o.z), "=f"(o.w) : "l"(acc[r][1]));
            __half2 h0 = __floats2half2_rn(o.x, o.y);
            __half2 h1 = __floats2half2_rn(o.z, o.w);
            uint2 pk = make_uint2(*(unsigned*)&h0, *(unsigned*)&h1);
            *(uint2*)(C + (size_t)row * D + tx * 4) = pk;
        }
    }
}

// ---------------- CSR gather-aggregate (half-warp per edge, uint4 loads) -------
// 16 lanes x 16B cover one fp16 row; the two half-warps process consecutive
// edges. acc[8] fp32 per lane; shfl(16) combine at the end.

__device__ __forceinline__ void acc8(float* acc, float w, uint4 v) {
    float2 f0 = __half22float2(*(__half2*)&v.x);
    float2 f1 = __half22float2(*(__half2*)&v.y);
    float2 f2 = __half22float2(*(__half2*)&v.z);
    float2 f3 = __half22float2(*(__half2*)&v.w);
    acc[0] += w * f0.x; acc[1] += w * f0.y;
    acc[2] += w * f1.x; acc[3] += w * f1.y;
    acc[4] += w * f2.x; acc[5] += w * f2.y;
    acc[6] += w * f3.x; acc[7] += w * f3.y;
}

// accumulate m * sum_{edges} w_e * h[src_e] into acc (lane covers 16B slice)
__device__ __forceinline__ void agg_list_hw(const __half* __restrict__ h,
                                            const int2* __restrict__ eds,
                                            int j, int end, float m,
                                            int half_id, int col8, float* acc) {
    // 4-edge unrolled main loop (2 independent LDG.128 per lane)
    for (; j + 3 < end; j += 4) {
        int2 e0 = __ldg(eds + j + half_id);
        int2 e1 = __ldg(eds + j + 2 + half_id);
        uint4 v0 = __ldg((const uint4*)(h + (size_t)e0.x * D) + col8);
        uint4 v1 = __ldg((const uint4*)(h + (size_t)e1.x * D) + col8);
        acc8(acc, m * __int_as_float(e0.y), v0);
        acc8(acc, m * __int_as_float(e1.y), v1);
    }
    // 2-edge step
    if (j + 1 < end) {
        int2 e0 = __ldg(eds + j + half_id);
        uint4 v0 = __ldg((const uint4*)(h + (size_t)e0.x * D) + col8);
        acc8(acc, m * __int_as_float(e0.y), v0);
        j += 2;
    }
    // single tail edge: half-warp 0 only
    if (j < end && half_id == 0) {
        int2 e0 = __ldg(eds + j);
        uint4 v0 = __ldg((const uint4*)(h + (size_t)e0.x * D) + col8);
        acc8(acc, m * __int_as_float(e0.y), v0);
    }
}

template <bool RELU>
__global__ void __launch_bounds__(256) k_agg_user(
    const __half* __restrict__ hF, const __half* __restrict__ hV,
    const float* __restrict__ bF, const float* __restrict__ bV,
    float* __restrict__ outp) {
    int warp = (blockIdx.x * blockDim.x + threadIdx.x) >> 5;
    if (warp >= NU) return;
    int lane = threadIdx.x & 31;
    int half_id = lane >> 4;
    int col8 = lane & 15;

    float acc[8];
#pragma unroll
    for (int k = 0; k < 8; k++) acc[k] = 0.f;

    float mF = 0.5f * g_inv_fd[warp];
    float mV = 0.5f * g_inv_vd[warp];
    agg_list_hw(hF, g_ef, g_off_f[warp], g_off_f[warp + 1], mF, half_id, col8, acc);
    agg_list_hw(hV, g_ev, g_off_v[warp], g_off_v[warp + 1], mV, half_id, col8, acc);

#pragma unroll
    for (int k = 0; k < 8; k++)
        acc[k] += __shfl_down_sync(0xffffffff, acc[k], 16);

    if (half_id == 0) {
        float4 b10 = __ldg((const float4*)bF + col8 * 2);
        float4 b11 = __ldg((const float4*)bF + col8 * 2 + 1);
        float4 b20 = __ldg((const float4*)bV + col8 * 2);
        float4 b21 = __ldg((const float4*)bV + col8 * 2 + 1);
        float4 o0, o1;
        o0.x = acc[0] + 0.5f * (b10.x + b20.x);
        o0.y = acc[1] + 0.5f * (b10.y + b20.y);
        o0.z = acc[2] + 0.5f * (b10.z + b20.z);
        o0.w = acc[3] + 0.5f * (b10.w + b20.w);
        o1.x = acc[4] + 0.5f * (b11.x + b21.x);
        o1.y = acc[5] + 0.5f * (b11.y + b21.y);
        o1.z = acc[6] + 0.5f * (b11.z + b21.z);
        o1.w = acc[7] + 0.5f * (b11.w + b21.w);
        if (RELU) {
            o0.x = fmaxf(o0.x, 0.f); o0.y = fmaxf(o0.y, 0.f);
            o0.z = fmaxf(o0.z, 0.f); o0.w = fmaxf(o0.w, 0.f);
            o1.x = fmaxf(o1.x, 0.f); o1.y = fmaxf(o1.y, 0.f);
            o1.z = fmaxf(o1.z, 0.f); o1.w = fmaxf(o1.w, 0.f);
        }
        float4* orow = (float4*)(outp + (size_t)warp * D) + col8 * 2;
        orow[0] = o0;
        orow[1] = o1;
    }
}

template <bool RELU>
__global__ void __launch_bounds__(256) k_agg_item(
    const __half* __restrict__ h, const float* __restrict__ b,
    float* __restrict__ outp) {
    int warp = (blockIdx.x * blockDim.x + threadIdx.x) >> 5;
    if (warp >= NI) return;
    int lane = threadIdx.x & 31;
    int half_id = lane >> 4;
    int col8 = lane & 15;

    float acc[8];
#pragma unroll
    for (int k = 0; k < 8; k++) acc[k] = 0.f;

    float m = g_inv_rd[warp];
    agg_list_hw(h, g_er, g_off_r[warp], g_off_r[warp + 1], m, half_id, col8, acc);

#pragma unroll
    for (int k = 0; k < 8; k++)
        acc[k] += __shfl_down_sync(0xffffffff, acc[k], 16);

    if (half_id == 0) {
        float4 b0 = __ldg((const float4*)b + col8 * 2);
        float4 b1 = __ldg((const float4*)b + col8 * 2 + 1);
        float4 o0, o1;
        o0.x = acc[0] + b0.x; o0.y = acc[1] + b0.y;
        o0.z = acc[2] + b0.z; o0.w = acc[3] + b0.w;
        o1.x = acc[4] + b1.x; o1.y = acc[5] + b1.y;
        o1.z = acc[6] + b1.z; o1.w = acc[7] + b1.w;
        if (RELU) {
            o0.x = fmaxf(o0.x, 0.f); o0.y = fmaxf(o0.y, 0.f);
            o0.z = fmaxf(o0.z, 0.f); o0.w = fmaxf(o0.w, 0.f);
            o1.x = fmaxf(o1.x, 0.f); o1.y = fmaxf(o1.y, 0.f);
            o1.z = fmaxf(o1.z, 0.f); o1.w = fmaxf(o1.w, 0.f);
        }
        float4* orow = (float4*)(outp + (size_t)warp * D) + col8 * 2;
        orow[0] = o0;
        orow[1] = o1;
    }
}

// ---------------- host driver --------------------------------------------------

extern "C" void kernel_launch(void* const* d_in, const int* in_sizes, int n_in,
                              void* d_out, int out_size) {
    const float* x_user = (const float*)d_in[0];
    const float* x_item = (const float*)d_in[1];
    const int* f_src = (const int*)d_in[2];
    const int* f_dst = (const int*)d_in[3];
    const int* r_src = (const int*)d_in[4];
    const int* r_dst = (const int*)d_in[5];
    const int* v_src = (const int*)d_in[6];
    const int* v_dst = (const int*)d_in[7];

    const float *W1f, *W1r, *W1v, *W2f, *W2r, *W2v;
    const float *b1f, *b1r, *b1v, *b2f, *b2r, *b2v;
    if (in_sizes[9] == 128 * 128) {
        W1f = (const float*)d_in[8];  W1r = (const float*)d_in[9];  W1v = (const float*)d_in[10];
        W2f = (const float*)d_in[11]; W2r = (const float*)d_in[12]; W2v = (const float*)d_in[13];
        b1f = (const float*)d_in[14]; b1r = (const float*)d_in[15]; b1v = (const float*)d_in[16];
        b2f = (const float*)d_in[17]; b2r = (const float*)d_in[18]; b2v = (const float*)d_in[19];
    } else {
        W1f = (const float*)d_in[8];  b1f = (const float*)d_in[9];
        W1r = (const float*)d_in[10]; b1r = (const float*)d_in[11];
        W1v = (const float*)d_in[12]; b1v = (const float*)d_in[13];
        W2f = (const float*)d_in[14]; b2f = (const float*)d_in[15];
        W2r = (const float*)d_in[16]; b2r = (const float*)d_in[17];
        W2v = (const float*)d_in[18]; b2v = (const float*)d_in[19];
    }
    float* out = (float*)d_out;

    __half *hu1, *hu2, *hi, *hu1b, *hu2b, *hib;
    float *u, *it;
    cudaGetSymbolAddress((void**)&hu1, g_hu1);
    cudaGetSymbolAddress((void**)&hu2, g_hu2);
    cudaGetSymbolAddress((void**)&hi,  g_hi);
    cudaGetSymbolAddress((void**)&hu1b, g_hu1b);
    cudaGetSymbolAddress((void**)&hu2b, g_hu2b);
    cudaGetSymbolAddress((void**)&hib,  g_hib);
    cudaGetSymbolAddress((void**)&u,  g_u);
    cudaGetSymbolAddress((void**)&it, g_it);

    static cudaStream_t s1 = 0, s2 = 0;
    static cudaEvent_t evFork = 0, evCSR = 0, evHu2 = 0, evU = 0, evItG = 0,
                       evHu2b = 0, evEnd = 0;
    if (s1 == 0) {
        cudaStreamCreateWithFlags(&s1, cudaStreamNonBlocking);
        cudaStreamCreateWithFlags(&s2, cudaStreamNonBlocking);
        cudaEventCreateWithFlags(&evFork, cudaEventDisableTiming);
        cudaEventCreateWithFlags(&evCSR,  cudaEventDisableTiming);
        cudaEventCreateWithFlags(&evHu2,  cudaEventDisableTiming);
        cudaEventCreateWithFlags(&evU,    cudaEventDisableTiming);
        cudaEventCreateWithFlags(&evItG,  cudaEventDisableTiming);
        cudaEventCreateWithFlags(&evHu2b, cudaEventDisableTiming);
        cudaEventCreateWithFlags(&evEnd,  cudaEventDisableTiming);
    }

    const int TB = 256;
    cudaFuncSetAttribute(k_gemm, cudaFuncAttributeMaxDynamicSharedMemorySize, GEMM_SMEM);

    int gNU   = (NU + TB - 1) / TB;
    int gAggU = (NU * 32 + TB - 1) / TB;
    int gAggI = (NI * 32 + TB - 1) / TB;
    int nbU = (NU + 1023) / 1024;

    dim3 gEdge3((NE + TB - 1) / TB, 3);
    dim3 gScan1(nbU, 3);
    dim3 gScan3((NU + 1 + TB - 1) / TB, 3);

    // ---- fork: CSR build on s1 (DRAM/atomic-bound) --------------------------
    cudaEventRecord(evFork, 0);
    cudaStreamWaitEvent(s1, evFork, 0);
    cudaStreamWaitEvent(s2, evFork, 0);
    k_zero_hists<<<gNU, TB, 0, s1>>>();
    k_hist3<<<gEdge3, TB, 0, s1>>>(f_src, f_dst, r_src, r_dst, v_src, v_dst);
    k_inv_all<<<gNU, TB, 0, s1>>>();
    k_scan1<<<gScan1, 1024, 0, s1>>>();
    k_scan2<<<3, 1024, 0, s1>>>();
    k_scan3<<<gScan3, TB, 0, s1>>>();
    k_fill3<<<gEdge3, TB, 0, s1>>>(f_src, f_dst, r_src, r_dst, v_src, v_dst);
    cudaEventRecord(evCSR, s1);

    // ---- legacy: layer-1 GEMMs (fma-bound, overlaps CSR) ---------------------
    k_gemm<<<(NU + 63) / 64, 256, GEMM_SMEM>>>(x_user, W1r, hu2, NU);
    cudaEventRecord(evHu2, 0);
    k_gemm<<<(NU + 63) / 64, 256, GEMM_SMEM>>>(x_user, W1f, hu1, NU);
    k_gemm<<<(NI + 63) / 64, 256, GEMM_SMEM>>>(x_item, W1v, hi,  NI);

    // ---- item pipeline on s1: agg_item1 -> it@W2v ----------------------------
    cudaStreamWaitEvent(s1, evHu2, 0);
    k_agg_item<true><<<gAggI, TB, 0, s1>>>(hu2, b1r, it);
    k_gemm<<<(NI + 63) / 64, 256, GEMM_SMEM, s1>>>(it, W2v, hib, NI);
    cudaEventRecord(evItG, s1);

    // ---- user pipeline on legacy: agg1 -> W2f ---------------------------------
    cudaStreamWaitEvent(0, evCSR, 0);
    k_agg_user<true><<<gAggU, TB>>>(hu1, hi, b1f, b1v, u);
    cudaEventRecord(evU, 0);
    k_gemm<<<(NU + 63) / 64, 256, GEMM_SMEM>>>(u, W2f, hu1b, NU);

    // ---- W2r on s2 (off s0's critical path; overlaps agg_user2) ---------------
    cudaStreamWaitEvent(s2, evU, 0);
    k_gemm<<<(NU + 63) / 64, 256, GEMM_SMEM, s2>>>(u, W2r, hu2b, NU);
    cudaEventRecord(evHu2b, s2);

    // ---- final item agg on s1 (needs hu2b from s2) -----------------------------
    cudaStreamWaitEvent(s1, evHu2b, 0);
    k_agg_item<false><<<gAggI, TB, 0, s1>>>(hu2b, b2r, out + (size_t)NU * D);
    cudaEventRecord(evEnd, s1);

    // ---- final user agg on s0: needs hu1b (in-order) + hib (evItG) -------------
    cudaStreamWaitEvent(0, evItG, 0);
    k_agg_user<false><<<gAggU, TB>>>(hu1b, hib, b2f, b2v, out);
    cudaStreamWaitEvent(0, evEnd, 0);  // join
}

// round 12
// speedup vs baseline: 1.6359x; 1.0554x over previous
#include <cuda_runtime.h>
#include <cuda_fp16.h>

#define NU 100000
#define NI 50000
#define NE 1600000
#define D  128

// ---------------- scratch (device globals) ----------------------------------
__device__ int g_h_fs[NU];
__device__ int g_h_fd[NU];
__device__ int g_h_rs[NU];
__device__ int g_h_rd[NI];
__device__ int g_h_vs[NI];
__device__ int g_h_vd[NU];

__device__ float g_inv_fs[NU];
__device__ float g_inv_fd[NU];
__device__ float g_inv_rs[NU];
__device__ float g_inv_rd[NI];
__device__ float g_inv_vs[NI];
__device__ float g_inv_vd[NU];

// combined user CSR (follows + rev, fully folded weights), item CSR (rates)
__device__ int   g_off_c[NU + 1];
__device__ int   g_off_r[NI + 1];
__device__ int   g_pos_c[NU];
__device__ int   g_pos_r[NI];
__device__ int2  g_ec[2 * NE];   // {src' (rev: NU+src), w_bits = full coeff}
__device__ int2  g_er[NE];
__device__ int   g_bsum[2][1024];

// layer h-buffers: user rows [0,NU), item rows [NU,NU+NI) contiguous
__device__ __half g_hc1[(size_t)(NU + NI) * D];
__device__ __half g_hc2[(size_t)(NU + NI) * D];
__device__ __half g_hu2 [(size_t)NU * D];
__device__ __half g_hu2b[(size_t)NU * D];
__device__ float  g_u  [(size_t)NU * D];
__device__ float  g_it [(size_t)NI * D];

// ---------------- setup kernels ----------------------------------------------

__global__ void k_zero_hists() {
    int i = blockIdx.x * blockDim.x + threadIdx.x;
    if (i < NU) { g_h_fs[i] = 0; g_h_fd[i] = 0; g_h_rs[i] = 0; g_h_vd[i] = 0; }
    if (i < NI) { g_h_rd[i] = 0; g_h_vs[i] = 0; }
}

__global__ void k_hist3(const int* __restrict__ fs, const int* __restrict__ fd,
                        const int* __restrict__ rs, const int* __restrict__ rd,
                        const int* __restrict__ vs, const int* __restrict__ vd) {
    int e = blockIdx.x * blockDim.x + threadIdx.x;
    if (e >= NE) return;
    if (blockIdx.y == 0) {
        atomicAdd(&g_h_fs[fs[e]], 1);
        atomicAdd(&g_h_fd[fd[e]], 1);
    } else if (blockIdx.y == 1) {
        atomicAdd(&g_h_rs[rs[e]], 1);
        atomicAdd(&g_h_rd[rd[e]], 1);
    } else {
        atomicAdd(&g_h_vs[vs[e]], 1);
        atomicAdd(&g_h_vd[vd[e]], 1);
    }
}

__device__ __forceinline__ float invsq(int x) {
    return x > 0 ? rsqrtf((float)x) : 0.f;
}

__global__ void k_inv_all() {
    int i = blockIdx.x * blockDim.x + threadIdx.x;
    if (i < NU) {
        g_inv_fs[i] = invsq(g_h_fs[i]);
        g_inv_fd[i] = invsq(g_h_fd[i]);
        g_inv_rs[i] = invsq(g_h_rs[i]);
        g_inv_vd[i] = invsq(g_h_vd[i]);
    }
    if (i < NI) {
        g_inv_rd[i] = invsq(g_h_rd[i]);
        g_inv_vs[i] = invsq(g_h_vs[i]);
    }
}

// ---------------- exclusive scan (2 arrays per launch via blockIdx.y) ---------

__global__ void k_scan1() {
    __shared__ int s[1024];
    int tid = threadIdx.x;
    int i = blockIdx.x * 1024 + tid;
    int v;
    int* outp; int n;
    if (blockIdx.y == 0) {   // combined user-dst degree (follows + rev)
        n = NU; outp = g_off_c;
        v = (i < n) ? (g_h_fd[i] + g_h_vd[i]) : 0;
    } else {                 // item-dst degree (rates)
        n = NI; outp = g_off_r;
        v = (i < n) ? g_h_rd[i] : 0;
    }
    s[tid] = v;
    __syncthreads();
#pragma unroll
    for (int o = 1; o < 1024; o <<= 1) {
        int t = (tid >= o) ? s[tid - o] : 0;
        __syncthreads();
        s[tid] += t;
        __syncthreads();
    }
    if (i < n) outp[i] = s[tid] - v;
    if (tid == 1023) g_bsum[blockIdx.y][blockIdx.x] = s[1023];
}

__global__ void k_scan2() {
    __shared__ int s[1024];
    int nb = (blockIdx.x == 1) ? (NI + 1023) / 1024 : (NU + 1023) / 1024;
    int tid = threadIdx.x;
    int v = (tid < nb) ? g_bsum[blockIdx.x][tid] : 0;
    s[tid] = v;
    __syncthreads();
#pragma unroll
    for (int o = 1; o < 1024; o <<= 1) {
        int t = (tid >= o) ? s[tid - o] : 0;
        __syncthreads();
        s[tid] += t;
        __syncthreads();
    }
    if (tid < nb) g_bsum[blockIdx.x][tid] = s[tid] - v;
}

__global__ void k_scan3() {
    int* outp; int* pos; int n; int total;
    if (blockIdx.y == 0) { outp = g_off_c; pos = g_pos_c; n = NU; total = 2 * NE; }
    else                 { outp = g_off_r; pos = g_pos_r; n = NI; total = NE; }
    int i = blockIdx.x * blockDim.x + threadIdx.x;
    if (i < n) {
        int v = outp[i] + g_bsum[blockIdx.y][i >> 10];
        outp[i] = v;
        pos[i] = v;
    } else if (i == n) {
        outp[n] = total;
    }
}

// fill: weights fully folded (src-norm * dst-norm * [0.5 for mean relations])
__global__ void k_fill3(const int* __restrict__ fs, const int* __restrict__ fd,
                        const int* __restrict__ rs, const int* __restrict__ rd,
                        const int* __restrict__ vs, const int* __restrict__ vd) {
    int e = blockIdx.x * blockDim.x + threadIdx.x;
    if (e >= NE) return;
    if (blockIdx.y == 0) {            // follows: user->user
        int s = fs[e], d = fd[e];
        float w = 0.5f * g_inv_fs[s] * g_inv_fd[d];
        int p = atomicAdd(&g_pos_c[d], 1);
        g_ec[p] = make_int2(s, __float_as_int(w));
    } else if (blockIdx.y == 1) {     // rates: user->item
        int s = rs[e], d = rd[e];
        float w = g_inv_rs[s] * g_inv_rd[d];
        int p = atomicAdd(&g_pos_r[d], 1);
        g_er[p] = make_int2(s, __float_as_int(w));
    } else {                          // rev: item->user (src offset by NU)
        int s = vs[e], d = vd[e];
        float w = 0.5f * g_inv_vs[s] * g_inv_vd[d];
        int p = atomicAdd(&g_pos_c[d], 1);
        g_ec[p] = make_int2(NU + s, __float_as_int(w));
    }
}

// ---------------- GEMM: C[n,128](fp16) = A[n,128](fp32) @ W[128,128](fp32) ----
// Row-pair f32x2 accumulators: A pairs load natively from transposed smem
// (zero packing); only 4 W-broadcast packs per k-step. 23 instr/k, fma-bound.

#define GEMM_SMEM ((128 * 128 + 128 * 64) * 4)  // W 64KB + At 32KB

__global__ void __launch_bounds__(256) k_gemm(const float* __restrict__ A,
                                              const float* __restrict__ W,
                                              __half* __restrict__ C, int n) {
    extern __shared__ float sm[];
    float* Ws = sm;               // [128][128]
    float* At = sm + 128 * 128;   // [128 k][64 row]

    for (int i = threadIdx.x; i < 128 * 32; i += 256)
        ((float4*)Ws)[i] = ((const float4*)W)[i];

    int row0 = blockIdx.x * 64;
    for (int i = threadIdx.x; i < 64 * 32; i += 256) {
        int c = i >> 6;
        int r = i & 63;
        int row = row0 + r;
        float4 v = (row < n) ? ((const float4*)A)[(size_t)row * 32 + c]
                             : make_float4(0.f, 0.f, 0.f, 0.f);
        At[(4 * c + 0) * 64 + r] = v.x;
        At[(4 * c + 1) * 64 + r] = v.y;
        At[(4 * c + 2) * 64 + r] = v.z;
        At[(4 * c + 3) * 64 + r] = v.w;
    }
    __syncthreads();

    int ty = threadIdx.x >> 5;   // rows ty*8..ty*8+7
    int tx = threadIdx.x & 31;   // cols tx*4..tx*4+3

    // acc[p][c] = f32x2 {row 2p, row 2p+1} for col tx*4+c
    unsigned long long acc[4][4];
#pragma unroll
    for (int p = 0; p < 4; p++)
#pragma unroll
        for (int c = 0; c < 4; c++) acc[p][c] = 0ull;

    const float* at = At + ty * 8;
#pragma unroll 8
    for (int k = 0; k < 128; k++) {
        ulonglong2 a01 = *(const ulonglong2*)(at + k * 64);      // {r0,r1},{r2,r3}
        ulonglong2 a23 = *(const ulonglong2*)(at + k * 64 + 4);  // {r4,r5},{r6,r7}
        float4 wv = ((const float4*)(Ws + k * 128))[tx];
        unsigned long long wb0, wb1, wb2, wb3;
        asm("mov.b64 %0, {%1, %1};" : "=l"(wb0) : "f"(wv.x));
        asm("mov.b64 %0, {%1, %1};" : "=l"(wb1) : "f"(wv.y));
        asm("mov.b64 %0, {%1, %1};" : "=l"(wb2) : "f"(wv.z));
        asm("mov.b64 %0, {%1, %1};" : "=l"(wb3) : "f"(wv.w));
        asm("fma.rn.f32x2 %0, %1, %2, %0;" : "+l"(acc[0][0]) : "l"(a01.x), "l"(wb0));
        asm("fma.rn.f32x2 %0, %1, %2, %0;" : "+l"(acc[0][1]) : "l"(a01.x), "l"(wb1));
        asm("fma.rn.f32x2 %0, %1, %2, %0;" : "+l"(acc[0][2]) : "l"(a01.x), "l"(wb2));
        asm("fma.rn.f32x2 %0, %1, %2, %0;" : "+l"(acc[0][3]) : "l"(a01.x), "l"(wb3));
        asm("fma.rn.f32x2 %0, %1, %2, %0;" : "+l"(acc[1][0]) : "l"(a01.y), "l"(wb0));
        asm("fma.rn.f32x2 %0, %1, %2, %0;" : "+l"(acc[1][1]) : "l"(a01.y), "l"(wb1));
        asm("fma.rn.f32x2 %0, %1, %2, %0;" : "+l"(acc[1][2]) : "l"(a01.y), "l"(wb2));
        asm("fma.rn.f32x2 %0, %1, %2, %0;" : "+l"(acc[1][3]) : "l"(a01.y), "l"(wb3));
        asm("fma.rn.f32x2 %0, %1, %2, %0;" : "+l"(acc[2][0]) : "l"(a23.x), "l"(wb0));
        asm("fma.rn.f32x2 %0, %1, %2, %0;" : "+l"(acc[2][1]) : "l"(a23.x), "l"(wb1));
        asm("fma.rn.f32x2 %0, %1, %2, %0;" : "+l"(acc[2][2]) : "l"(a23.x), "l"(wb2));
        asm("fma.rn.f32x2 %0, %1, %2, %0;" : "+l"(acc[2][3]) : "l"(a23.x), "l"(wb3));
        asm("fma.rn.f32x2 %0, %1, %2, %0;" : "+l"(acc[3][0]) : "l"(a23.y), "l"(wb0));
        asm("fma.rn.f32x2 %0, %1, %2, %0;" : "+l"(acc[3][1]) : "l"(a23.y), "l"(wb1));
        asm("fma.rn.f32x2 %0, %1, %2, %0;" : "+l"(acc[3][2]) : "l"(a23.y), "l"(wb2));
        asm("fma.rn.f32x2 %0, %1, %2, %0;" : "+l"(acc[3][3]) : "l"(a23.y), "l"(wb3));
    }

#pragma unroll
    for (int p = 0; p < 4; p++) {
        float e0, o0, e1, o1, e2, o2, e3, o3;
        asm("mov.b64 {%0, %1}, %2;" : "=f"(e0), "=f"(o0) : "l"(acc[p][0]));
        asm("mov.b64 {%0, %1}, %2;" : "=f"(e1), "=f"(o1) : "l"(acc[p][1]));
        asm("mov.b64 {%0, %1}, %2;" : "=f"(e2), "=f"(o2) : "l"(acc[p][2]));
        asm("mov.b64 {%0, %1}, %2;" : "=f"(e3), "=f"(o3) : "l"(acc[p][3]));
        int row = row0 + ty * 8 + 2 * p;
        if (row < n) {
            __half2 h0 = __floats2half2_rn(e0, e1);
            __half2 h1 = __floats2half2_rn(e2, e3);
            *(uint2*)(C + (size_t)row * D + tx * 4) =
                make_uint2(*(unsigned*)&h0, *(unsigned*)&h1);
        }
        if (row + 1 < n) {
            __half2 h0 = __floats2half2_rn(o0, o1);
            __half2 h1 = __floats2half2_rn(o2, o3);
            *(uint2*)(C + (size_t)(row + 1) * D + tx * 4) =
                make_uint2(*(unsigned*)&h0, *(unsigned*)&h1);
        }
    }
}

// ---------------- CSR gather-aggregate (half-warp per edge, folded weights) ----

__device__ __forceinline__ void acc8(float* acc, float w, uint4 v) {
    float2 f0 = __half22float2(*(__half2*)&v.x);
    float2 f1 = __half22float2(*(__half2*)&v.y);
    float2 f2 = __half22float2(*(__half2*)&v.z);
    float2 f3 = __half22float2(*(__half2*)&v.w);
    acc[0] += w * f0.x; acc[1] += w * f0.y;
    acc[2] += w * f1.x; acc[3] += w * f1.y;
    acc[4] += w * f2.x; acc[5] += w * f2.y;
    acc[6] += w * f3.x; acc[7] += w * f3.y;
}

__device__ __forceinline__ void agg_list_hw(const __half* __restrict__ h,
                                            const int2* __restrict__ eds,
                                            int j, int end,
                                            int half_id, int col8, float* acc) {
    for (; j + 3 < end; j += 4) {
        int2 e0 = __ldg(eds + j + half_id);
        int2 e1 = __ldg(eds + j + 2 + half_id);
        uint4 v0 = __ldg((const uint4*)(h + (size_t)e0.x * D) + col8);
        uint4 v1 = __ldg((const uint4*)(h + (size_t)e1.x * D) + col8);
        acc8(acc, __int_as_float(e0.y), v0);
        acc8(acc, __int_as_float(e1.y), v1);
    }
    if (j + 1 < end) {
        int2 e0 = __ldg(eds + j + half_id);
        uint4 v0 = __ldg((const uint4*)(h + (size_t)e0.x * D) + col8);
        acc8(acc, __int_as_float(e0.y), v0);
        j += 2;
    }
    if (j < end && half_id == 0) {
        int2 e0 = __ldg(eds + j);
        uint4 v0 = __ldg((const uint4*)(h + (size_t)e0.x * D) + col8);
        acc8(acc, __int_as_float(e0.y), v0);
    }
}

template <bool RELU>
__global__ void __launch_bounds__(256) k_agg_user(
    const __half* __restrict__ h,   // combined [NU+NI] rows
    const float* __restrict__ bF, const float* __restrict__ bV,
    float* __restrict__ outp) {
    int warp = (blockIdx.x * blockDim.x + threadIdx.x) >> 5;
    if (warp >= NU) return;
    int lane = threadIdx.x & 31;
    int half_id = lane >> 4;
    int col8 = lane & 15;

    float acc[8];
#pragma unroll
    for (int k = 0; k < 8; k++) acc[k] = 0.f;

    agg_list_hw(h, g_ec, g_off_c[warp], g_off_c[warp + 1], half_id, col8, acc);

#pragma unroll
    for (int k = 0; k < 8; k++)
        acc[k] += __shfl_down_sync(0xffffffff, acc[k], 16);

    if (half_id == 0) {
        float4 b10 = __ldg((const float4*)bF + col8 * 2);
        float4 b11 = __ldg((const float4*)bF + col8 * 2 + 1);
        float4 b20 = __ldg((const float4*)bV + col8 * 2);
        float4 b21 = __ldg((const float4*)bV + col8 * 2 + 1);
        float4 o0, o1;
        o0.x = acc[0] + 0.5f * (b10.x + b20.x);
        o0.y = acc[1] + 0.5f * (b10.y + b20.y);
        o0.z = acc[2] + 0.5f * (b10.z + b20.z);
        o0.w = acc[3] + 0.5f * (b10.w + b20.w);
        o1.x = acc[4] + 0.5f * (b11.x + b21.x);
        o1.y = acc[5] + 0.5f * (b11.y + b21.y);
        o1.z = acc[6] + 0.5f * (b11.z + b21.z);
        o1.w = acc[7] + 0.5f * (b11.w + b21.w);
        if (RELU) {
            o0.x = fmaxf(o0.x, 0.f); o0.y = fmaxf(o0.y, 0.f);
            o0.z = fmaxf(o0.z, 0.f); o0.w = fmaxf(o0.w, 0.f);
            o1.x = fmaxf(o1.x, 0.f); o1.y = fmaxf(o1.y, 0.f);
            o1.z = fmaxf(o1.z, 0.f); o1.w = fmaxf(o1.w, 0.f);
        }
        float4* orow = (float4*)(outp + (size_t)warp * D) + col8 * 2;
        orow[0] = o0;
        orow[1] = o1;
    }
}

template <bool RELU>
__global__ void __launch_bounds__(256) k_agg_item(
    const __half* __restrict__ h, const float* __restrict__ b,
    float* __restrict__ outp) {
    int warp = (blockIdx.x * blockDim.x + threadIdx.x) >> 5;
    if (warp >= NI) return;
    int lane = threadIdx.x & 31;
    int half_id = lane >> 4;
    int col8 = lane & 15;

    float acc[8];
#pragma unroll
    for (int k = 0; k < 8; k++) acc[k] = 0.f;

    agg_list_hw(h, g_er, g_off_r[warp], g_off_r[warp + 1], half_id, col8, acc);

#pragma unroll
    for (int k = 0; k < 8; k++)
        acc[k] += __shfl_down_sync(0xffffffff, acc[k], 16);

    if (half_id == 0) {
        float4 b0 = __ldg((const float4*)b + col8 * 2);
        float4 b1 = __ldg((const float4*)b + col8 * 2 + 1);
        float4 o0, o1;
        o0.x = acc[0] + b0.x; o0.y = acc[1] + b0.y;
        o0.z = acc[2] + b0.z; o0.w = acc[3] + b0.w;
        o1.x = acc[4] + b1.x; o1.y = acc[5] + b1.y;
        o1.z = acc[6] + b1.z; o1.w = acc[7] + b1.w;
        if (RELU) {
            o0.x = fmaxf(o0.x, 0.f); o0.y = fmaxf(o0.y, 0.f);
            o0.z = fmaxf(o0.z, 0.f); o0.w = fmaxf(o0.w, 0.f);
            o1.x = fmaxf(o1.x, 0.f); o1.y = fmaxf(o1.y, 0.f);
            o1.z = fmaxf(o1.z, 0.f); o1.w = fmaxf(o1.w, 0.f);
        }
        float4* orow = (float4*)(outp + (size_t)warp * D) + col8 * 2;
        orow[0] = o0;
        orow[1] = o1;
    }
}

// ---------------- host driver --------------------------------------------------

extern "C" void kernel_launch(void* const* d_in, const int* in_sizes, int n_in,
                              void* d_out, int out_size) {
    const float* x_user = (const float*)d_in[0];
    const float* x_item = (const float*)d_in[1];
    const int* f_src = (const int*)d_in[2];
    const int* f_dst = (const int*)d_in[3];
    const int* r_src = (const int*)d_in[4];
    const int* r_dst = (const int*)d_in[5];
    const int* v_src = (const int*)d_in[6];
    const int* v_dst = (const int*)d_in[7];

    const float *W1f, *W1r, *W1v, *W2f, *W2r, *W2v;
    const float *b1f, *b1r, *b1v, *b2f, *b2r, *b2v;
    if (in_sizes[9] == 128 * 128) {
        W1f = (const float*)d_in[8];  W1r = (const float*)d_in[9];  W1v = (const float*)d_in[10];
        W2f = (const float*)d_in[11]; W2r = (const float*)d_in[12]; W2v = (const float*)d_in[13];
        b1f = (const float*)d_in[14]; b1r = (const float*)d_in[15]; b1v = (const float*)d_in[16];
        b2f = (const float*)d_in[17]; b2r = (const float*)d_in[18]; b2v = (const float*)d_in[19];
    } else {
        W1f = (const float*)d_in[8];  b1f = (const float*)d_in[9];
        W1r = (const float*)d_in[10]; b1r = (const float*)d_in[11];
        W1v = (const float*)d_in[12]; b1v = (const float*)d_in[13];
        W2f = (const float*)d_in[14]; b2f = (const float*)d_in[15];
        W2r = (const float*)d_in[16]; b2r = (const float*)d_in[17];
        W2v = (const float*)d_in[18]; b2v = (const float*)d_in[19];
    }
    float* out = (float*)d_out;

    __half *hc1, *hc2, *hu2, *hu2b;
    float *u, *it;
    cudaGetSymbolAddress((void**)&hc1, g_hc1);
    cudaGetSymbolAddress((void**)&hc2, g_hc2);
    cudaGetSymbolAddress((void**)&hu2, g_hu2);
    cudaGetSymbolAddress((void**)&hu2b, g_hu2b);
    cudaGetSymbolAddress((void**)&u,  g_u);
    cudaGetSymbolAddress((void**)&it, g_it);
    __half* hu1 = hc1;
    __half* hi  = hc1 + (size_t)NU * D;
    __half* hu1b = hc2;
    __half* hib  = hc2 + (size_t)NU * D;

    static cudaStream_t s1 = 0, s2 = 0;
    static cudaEvent_t evFork = 0, evCSR = 0, evHu2 = 0, evU = 0, evItG = 0,
                       evHu2b = 0, evEnd = 0;
    if (s1 == 0) {
        cudaStreamCreateWithFlags(&s1, cudaStreamNonBlocking);
        cudaStreamCreateWithFlags(&s2, cudaStreamNonBlocking);
        cudaEventCreateWithFlags(&evFork, cudaEventDisableTiming);
        cudaEventCreateWithFlags(&evCSR,  cudaEventDisableTiming);
        cudaEventCreateWithFlags(&evHu2,  cudaEventDisableTiming);
        cudaEventCreateWithFlags(&evU,    cudaEventDisableTiming);
        cudaEventCreateWithFlags(&evItG,  cudaEventDisableTiming);
        cudaEventCreateWithFlags(&evHu2b, cudaEventDisableTiming);
        cudaEventCreateWithFlags(&evEnd,  cudaEventDisableTiming);
    }

    const int TB = 256;
    cudaFuncSetAttribute(k_gemm, cudaFuncAttributeMaxDynamicSharedMemorySize, GEMM_SMEM);

    int gNU   = (NU + TB - 1) / TB;
    int gAggU = (NU * 32 + TB - 1) / TB;
    int gAggI = (NI * 32 + TB - 1) / TB;
    int nbU = (NU + 1023) / 1024;

    dim3 gEdge3((NE + TB - 1) / TB, 3);
    dim3 gScan1(nbU, 2);
    dim3 gScan3((NU + 1 + TB - 1) / TB, 2);

    // ---- fork: CSR build on s1 (DRAM/atomic-bound) --------------------------
    cudaEventRecord(evFork, 0);
    cudaStreamWaitEvent(s1, evFork, 0);
    cudaStreamWaitEvent(s2, evFork, 0);
    k_zero_hists<<<gNU, TB, 0, s1>>>();
    k_hist3<<<gEdge3, TB, 0, s1>>>(f_src, f_dst, r_src, r_dst, v_src, v_dst);
    k_inv_all<<<gNU, TB, 0, s1>>>();
    k_scan1<<<gScan1, 1024, 0, s1>>>();
    k_scan2<<<2, 1024, 0, s1>>>();
    k_scan3<<<gScan3, TB, 0, s1>>>();
    k_fill3<<<gEdge3, TB, 0, s1>>>(f_src, f_dst, r_src, r_dst, v_src, v_dst);
    cudaEventRecord(evCSR, s1);

    // ---- legacy: layer-1 GEMMs (fma-bound, overlaps CSR) ---------------------
    k_gemm<<<(NU + 63) / 64, 256, GEMM_SMEM>>>(x_user, W1r, hu2, NU);
    cudaEventRecord(evHu2, 0);
    k_gemm<<<(NU + 63) / 64, 256, GEMM_SMEM>>>(x_user, W1f, hu1, NU);
    k_gemm<<<(NI + 63) / 64, 256, GEMM_SMEM>>>(x_item, W1v, hi,  NI);

    // ---- item pipeline on s1: agg_item1 -> it@W2v ----------------------------
    cudaStreamWaitEvent(s1, evHu2, 0);
    k_agg_item<true><<<gAggI, TB, 0, s1>>>(hu2, b1r, it);
    k_gemm<<<(NI + 63) / 64, 256, GEMM_SMEM, s1>>>(it, W2v, hib, NI);
    cudaEventRecord(evItG, s1);

    // ---- user pipeline on legacy: agg1 -> W2f ---------------------------------
    cudaStreamWaitEvent(0, evCSR, 0);
    k_agg_user<true><<<gAggU, TB>>>(hc1, b1f, b1v, u);
    cudaEventRecord(evU, 0);
    k_gemm<<<(NU + 63) / 64, 256, GEMM_SMEM>>>(u, W2f, hu1b, NU);

    // ---- W2r on s2 (off s0's critical path; overlaps agg_user2) ---------------
    cudaStreamWaitEvent(s2, evU, 0);
    k_gemm<<<(NU + 63) / 64, 256, GEMM_SMEM, s2>>>(u, W2r, hu2b, NU);
    cudaEventRecord(evHu2b, s2);

    // ---- final item agg on s1 (needs hu2b from s2) -----------------------------
    cudaStreamWaitEvent(s1, evHu2b, 0);
    k_agg_item<false><<<gAggI, TB, 0, s1>>>(hu2b, b2r, out + (size_t)NU * D);
    cudaEventRecord(evEnd, s1);

    // ---- final user agg on s0: needs hu1b (in-order) + hib (evItG) -------------
    cudaStreamWaitEvent(0, evItG, 0);
    k_agg_user<false><<<gAggU, TB>>>(hc2, b2f, b2v, out);
    cudaStreamWaitEvent(0, evEnd, 0);  // join
}

// round 13
// speedup vs baseline: 1.6379x; 1.0012x over previous
#include <cuda_runtime.h>
#include <cuda_fp16.h>

#define NU 100000
#define NI 50000
#define NE 1600000
#define D  128

// ---------------- scratch (device globals) ----------------------------------
__device__ int g_h_fs[NU];
__device__ int g_h_fd[NU];
__device__ int g_h_rs[NU];
__device__ int g_h_rd[NI];
__device__ int g_h_vs[NI];
__device__ int g_h_vd[NU];

__device__ float g_inv_fs[NU];
__device__ float g_inv_fd[NU];
__device__ float g_inv_rs[NU];
__device__ float g_inv_rd[NI];
__device__ float g_inv_vs[NI];
__device__ float g_inv_vd[NU];

// combined user CSR (follows + rev, fully folded weights), item CSR (rates)
__device__ int   g_off_c[NU + 1];
__device__ int   g_off_r[NI + 1];
__device__ int   g_pos_c[NU];
__device__ int   g_pos_r[NI];
__device__ int2  g_ec[2 * NE];   // {src' (rev: NU+src), w_bits = full coeff}
__device__ int2  g_er[NE];
__device__ int   g_bsum[2][1024];

// layer h-buffers: user rows [0,NU), item rows [NU,NU+NI) contiguous
__device__ __half g_hc1[(size_t)(NU + NI) * D];
__device__ __half g_hc2[(size_t)(NU + NI) * D];
__device__ __half g_hu2 [(size_t)NU * D];
__device__ __half g_hu2b[(size_t)NU * D];
__device__ float  g_u  [(size_t)NU * D];
__device__ float  g_it [(size_t)NI * D];

// ---------------- setup kernels ----------------------------------------------

__global__ void k_zero_hists() {
    int i = blockIdx.x * blockDim.x + threadIdx.x;
    if (i < NU) { g_h_fs[i] = 0; g_h_fd[i] = 0; g_h_rs[i] = 0; g_h_vd[i] = 0; }
    if (i < NI) { g_h_rd[i] = 0; g_h_vs[i] = 0; }
}

__global__ void k_hist3(const int* __restrict__ fs, const int* __restrict__ fd,
                        const int* __restrict__ rs, const int* __restrict__ rd,
                        const int* __restrict__ vs, const int* __restrict__ vd) {
    int e = blockIdx.x * blockDim.x + threadIdx.x;
    if (e >= NE) return;
    if (blockIdx.y == 0) {
        atomicAdd(&g_h_fs[fs[e]], 1);
        atomicAdd(&g_h_fd[fd[e]], 1);
    } else if (blockIdx.y == 1) {
        atomicAdd(&g_h_rs[rs[e]], 1);
        atomicAdd(&g_h_rd[rd[e]], 1);
    } else {
        atomicAdd(&g_h_vs[vs[e]], 1);
        atomicAdd(&g_h_vd[vd[e]], 1);
    }
}

__device__ __forceinline__ float invsq(int x) {
    return x > 0 ? rsqrtf((float)x) : 0.f;
}

__global__ void k_inv_all() {
    int i = blockIdx.x * blockDim.x + threadIdx.x;
    if (i < NU) {
        g_inv_fs[i] = invsq(g_h_fs[i]);
        g_inv_fd[i] = invsq(g_h_fd[i]);
        g_inv_rs[i] = invsq(g_h_rs[i]);
        g_inv_vd[i] = invsq(g_h_vd[i]);
    }
    if (i < NI) {
        g_inv_rd[i] = invsq(g_h_rd[i]);
        g_inv_vs[i] = invsq(g_h_vs[i]);
    }
}

// ---------------- exclusive scan (2 arrays per launch via blockIdx.y) ---------

__global__ void k_scan1() {
    __shared__ int s[1024];
    int tid = threadIdx.x;
    int i = blockIdx.x * 1024 + tid;
    int v;
    int* outp; int n;
    if (blockIdx.y == 0) {   // combined user-dst degree (follows + rev)
        n = NU; outp = g_off_c;
        v = (i < n) ? (g_h_fd[i] + g_h_vd[i]) : 0;
    } else {                 // item-dst degree (rates)
        n = NI; outp = g_off_r;
        v = (i < n) ? g_h_rd[i] : 0;
    }
    s[tid] = v;
    __syncthreads();
#pragma unroll
    for (int o = 1; o < 1024; o <<= 1) {
        int t = (tid >= o) ? s[tid - o] : 0;
        __syncthreads();
        s[tid] += t;
        __syncthreads();
    }
    if (i < n) outp[i] = s[tid] - v;
    if (tid == 1023) g_bsum[blockIdx.y][blockIdx.x] = s[1023];
}

__global__ void k_scan2() {
    __shared__ int s[1024];
    int nb = (blockIdx.x == 1) ? (NI + 1023) / 1024 : (NU + 1023) / 1024;
    int tid = threadIdx.x;
    int v = (tid < nb) ? g_bsum[blockIdx.x][tid] : 0;
    s[tid] = v;
    __syncthreads();
#pragma unroll
    for (int o = 1; o < 1024; o <<= 1) {
        int t = (tid >= o) ? s[tid - o] : 0;
        __syncthreads();
        s[tid] += t;
        __syncthreads();
    }
    if (tid < nb) g_bsum[blockIdx.x][tid] = s[tid] - v;
}

__global__ void k_scan3() {
    int* outp; int* pos; int n; int total;
    if (blockIdx.y == 0) { outp = g_off_c; pos = g_pos_c; n = NU; total = 2 * NE; }
    else                 { outp = g_off_r; pos = g_pos_r; n = NI; total = NE; }
    int i = blockIdx.x * blockDim.x + threadIdx.x;
    if (i < n) {
        int v = outp[i] + g_bsum[blockIdx.y][i >> 10];
        outp[i] = v;
        pos[i] = v;
    } else if (i == n) {
        outp[n] = total;
    }
}

// fill: weights fully folded (src-norm * dst-norm * [0.5 for mean relations])
__global__ void k_fill3(const int* __restrict__ fs, const int* __restrict__ fd,
                        const int* __restrict__ rs, const int* __restrict__ rd,
                        const int* __restrict__ vs, const int* __restrict__ vd) {
    int e = blockIdx.x * blockDim.x + threadIdx.x;
    if (e >= NE) return;
    if (blockIdx.y == 0) {            // follows: user->user
        int s = fs[e], d = fd[e];
        float w = 0.5f * g_inv_fs[s] * g_inv_fd[d];
        int p = atomicAdd(&g_pos_c[d], 1);
        g_ec[p] = make_int2(s, __float_as_int(w));
    } else if (blockIdx.y == 1) {     // rates: user->item
        int s = rs[e], d = rd[e];
        float w = g_inv_rs[s] * g_inv_rd[d];
        int p = atomicAdd(&g_pos_r[d], 1);
        g_er[p] = make_int2(s, __float_as_int(w));
    } else {                          // rev: item->user (src offset by NU)
        int s = vs[e], d = vd[e];
        float w = 0.5f * g_inv_vs[s] * g_inv_vd[d];
        int p = atomicAdd(&g_pos_c[d], 1);
        g_ec[p] = make_int2(NU + s, __float_as_int(w));
    }
}

// ---------------- GEMM: C[n,128](fp16) = A[n,128](fp32) @ W[128,128](fp32) ----
// Row-pair f32x2 accumulators (R12 kernel, unchanged).

#define GEMM_SMEM ((128 * 128 + 128 * 64) * 4)  // W 64KB + At 32KB

__global__ void __launch_bounds__(256) k_gemm(const float* __restrict__ A,
                                              const float* __restrict__ W,
                                              __half* __restrict__ C, int n) {
    extern __shared__ float sm[];
    float* Ws = sm;               // [128][128]
    float* At = sm + 128 * 128;   // [128 k][64 row]

    for (int i = threadIdx.x; i < 128 * 32; i += 256)
        ((float4*)Ws)[i] = ((const float4*)W)[i];

    int row0 = blockIdx.x * 64;
    for (int i = threadIdx.x; i < 64 * 32; i += 256) {
        int c = i >> 6;
        int r = i & 63;
        int row = row0 + r;
        float4 v = (row < n) ? ((const float4*)A)[(size_t)row * 32 + c]
                             : make_float4(0.f, 0.f, 0.f, 0.f);
        At[(4 * c + 0) * 64 + r] = v.x;
        At[(4 * c + 1) * 64 + r] = v.y;
        At[(4 * c + 2) * 64 + r] = v.z;
        At[(4 * c + 3) * 64 + r] = v.w;
    }
    __syncthreads();

    int ty = threadIdx.x >> 5;   // rows ty*8..ty*8+7
    int tx = threadIdx.x & 31;   // cols tx*4..tx*4+3

    unsigned long long acc[4][4];
#pragma unroll
    for (int p = 0; p < 4; p++)
#pragma unroll
        for (int c = 0; c < 4; c++) acc[p][c] = 0ull;

    const float* at = At + ty * 8;
#pragma unroll 8
    for (int k = 0; k < 128; k++) {
        ulonglong2 a01 = *(const ulonglong2*)(at + k * 64);
        ulonglong2 a23 = *(const ulonglong2*)(at + k * 64 + 4);
        float4 wv = ((const float4*)(Ws + k * 128))[tx];
        unsigned long long wb0, wb1, wb2, wb3;
        asm("mov.b64 %0, {%1, %1};" : "=l"(wb0) : "f"(wv.x));
        asm("mov.b64 %0, {%1, %1};" : "=l"(wb1) : "f"(wv.y));
        asm("mov.b64 %0, {%1, %1};" : "=l"(wb2) : "f"(wv.z));
        asm("mov.b64 %0, {%1, %1};" : "=l"(wb3) : "f"(wv.w));
        asm("fma.rn.f32x2 %0, %1, %2, %0;" : "+l"(acc[0][0]) : "l"(a01.x), "l"(wb0));
        asm("fma.rn.f32x2 %0, %1, %2, %0;" : "+l"(acc[0][1]) : "l"(a01.x), "l"(wb1));
        asm("fma.rn.f32x2 %0, %1, %2, %0;" : "+l"(acc[0][2]) : "l"(a01.x), "l"(wb2));
        asm("fma.rn.f32x2 %0, %1, %2, %0;" : "+l"(acc[0][3]) : "l"(a01.x), "l"(wb3));
        asm("fma.rn.f32x2 %0, %1, %2, %0;" : "+l"(acc[1][0]) : "l"(a01.y), "l"(wb0));
        asm("fma.rn.f32x2 %0, %1, %2, %0;" : "+l"(acc[1][1]) : "l"(a01.y), "l"(wb1));
        asm("fma.rn.f32x2 %0, %1, %2, %0;" : "+l"(acc[1][2]) : "l"(a01.y), "l"(wb2));
        asm("fma.rn.f32x2 %0, %1, %2, %0;" : "+l"(acc[1][3]) : "l"(a01.y), "l"(wb3));
        asm("fma.rn.f32x2 %0, %1, %2, %0;" : "+l"(acc[2][0]) : "l"(a23.x), "l"(wb0));
        asm("fma.rn.f32x2 %0, %1, %2, %0;" : "+l"(acc[2][1]) : "l"(a23.x), "l"(wb1));
        asm("fma.rn.f32x2 %0, %1, %2, %0;" : "+l"(acc[2][2]) : "l"(a23.x), "l"(wb2));
        asm("fma.rn.f32x2 %0, %1, %2, %0;" : "+l"(acc[2][3]) : "l"(a23.x), "l"(wb3));
        asm("fma.rn.f32x2 %0, %1, %2, %0;" : "+l"(acc[3][0]) : "l"(a23.y), "l"(wb0));
        asm("fma.rn.f32x2 %0, %1, %2, %0;" : "+l"(acc[3][1]) : "l"(a23.y), "l"(wb1));
        asm("fma.rn.f32x2 %0, %1, %2, %0;" : "+l"(acc[3][2]) : "l"(a23.y), "l"(wb2));
        asm("fma.rn.f32x2 %0, %1, %2, %0;" : "+l"(acc[3][3]) : "l"(a23.y), "l"(wb3));
    }

#pragma unroll
    for (int p = 0; p < 4; p++) {
        float e0, o0, e1, o1, e2, o2, e3, o3;
        asm("mov.b64 {%0, %1}, %2;" : "=f"(e0), "=f"(o0) : "l"(acc[p][0]));
        asm("mov.b64 {%0, %1}, %2;" : "=f"(e1), "=f"(o1) : "l"(acc[p][1]));
        asm("mov.b64 {%0, %1}, %2;" : "=f"(e2), "=f"(o2) : "l"(acc[p][2]));
        asm("mov.b64 {%0, %1}, %2;" : "=f"(e3), "=f"(o3) : "l"(acc[p][3]));
        int row = row0 + ty * 8 + 2 * p;
        if (row < n) {
            __half2 h0 = __floats2half2_rn(e0, e1);
            __half2 h1 = __floats2half2_rn(e2, e3);
            *(uint2*)(C + (size_t)row * D + tx * 4) =
                make_uint2(*(unsigned*)&h0, *(unsigned*)&h1);
        }
        if (row + 1 < n) {
            __half2 h0 = __floats2half2_rn(o0, o1);
            __half2 h1 = __floats2half2_rn(o2, o3);
            *(uint2*)(C + (size_t)(row + 1) * D + tx * 4) =
                make_uint2(*(unsigned*)&h0, *(unsigned*)&h1);
        }
    }
}

// ---------------- CSR gather-aggregate (half-warp per edge, folded weights) ----

__device__ __forceinline__ void acc8(float* acc, float w, uint4 v) {
    float2 f0 = __half22float2(*(__half2*)&v.x);
    float2 f1 = __half22float2(*(__half2*)&v.y);
    float2 f2 = __half22float2(*(__half2*)&v.z);
    float2 f3 = __half22float2(*(__half2*)&v.w);
    acc[0] += w * f0.x; acc[1] += w * f0.y;
    acc[2] += w * f1.x; acc[3] += w * f1.y;
    acc[4] += w * f2.x; acc[5] += w * f2.y;
    acc[6] += w * f3.x; acc[7] += w * f3.y;
}

__device__ __forceinline__ void agg_list_hw(const __half* __restrict__ h,
                                            const int2* __restrict__ eds,
                                            int j, int end,
                                            int half_id, int col8, float* acc) {
    for (; j + 3 < end; j += 4) {
        int2 e0 = __ldg(eds + j + half_id);
        int2 e1 = __ldg(eds + j + 2 + half_id);
        uint4 v0 = __ldg((const uint4*)(h + (size_t)e0.x * D) + col8);
        uint4 v1 = __ldg((const uint4*)(h + (size_t)e1.x * D) + col8);
        acc8(acc, __int_as_float(e0.y), v0);
        acc8(acc, __int_as_float(e1.y), v1);
    }
    if (j + 1 < end) {
        int2 e0 = __ldg(eds + j + half_id);
        uint4 v0 = __ldg((const uint4*)(h + (size_t)e0.x * D) + col8);
        acc8(acc, __int_as_float(e0.y), v0);
        j += 2;
    }
    if (j < end && half_id == 0) {
        int2 e0 = __ldg(eds + j);
        uint4 v0 = __ldg((const uint4*)(h + (size_t)e0.x * D) + col8);
        acc8(acc, __int_as_float(e0.y), v0);
    }
}

template <bool RELU>
__global__ void __launch_bounds__(256) k_agg_user(
    const __half* __restrict__ h,   // combined [NU+NI] rows
    const float* __restrict__ bF, const float* __restrict__ bV,
    float* __restrict__ outp) {
    int warp = (blockIdx.x * blockDim.x + threadIdx.x) >> 5;
    if (warp >= NU) return;
    int lane = threadIdx.x & 31;
    int half_id = lane >> 4;
    int col8 = lane & 15;

    float acc[8];
#pragma unroll
    for (int k = 0; k < 8; k++) acc[k] = 0.f;

    agg_list_hw(h, g_ec, g_off_c[warp], g_off_c[warp + 1], half_id, col8, acc);

#pragma unroll
    for (int k = 0; k < 8; k++)
        acc[k] += __shfl_down_sync(0xffffffff, acc[k], 16);

    if (half_id == 0) {
        float4 b10 = __ldg((const float4*)bF + col8 * 2);
        float4 b11 = __ldg((const float4*)bF + col8 * 2 + 1);
        float4 b20 = __ldg((const float4*)bV + col8 * 2);
        float4 b21 = __ldg((const float4*)bV + col8 * 2 + 1);
        float4 o0, o1;
        o0.x = acc[0] + 0.5f * (b10.x + b20.x);
        o0.y = acc[1] + 0.5f * (b10.y + b20.y);
        o0.z = acc[2] + 0.5f * (b10.z + b20.z);
        o0.w = acc[3] + 0.5f * (b10.w + b20.w);
        o1.x = acc[4] + 0.5f * (b11.x + b21.x);
        o1.y = acc[5] + 0.5f * (b11.y + b21.y);
        o1.z = acc[6] + 0.5f * (b11.z + b21.z);
        o1.w = acc[7] + 0.5f * (b11.w + b21.w);
        if (RELU) {
            o0.x = fmaxf(o0.x, 0.f); o0.y = fmaxf(o0.y, 0.f);
            o0.z = fmaxf(o0.z, 0.f); o0.w = fmaxf(o0.w, 0.f);
            o1.x = fmaxf(o1.x, 0.f); o1.y = fmaxf(o1.y, 0.f);
            o1.z = fmaxf(o1.z, 0.f); o1.w = fmaxf(o1.w, 0.f);
        }
        float4* orow = (float4*)(outp + (size_t)warp * D) + col8 * 2;
        orow[0] = o0;
        orow[1] = o1;
    }
}

template <bool RELU>
__global__ void __launch_bounds__(256) k_agg_item(
    const __half* __restrict__ h, const float* __restrict__ b,
    float* __restrict__ outp) {
    int warp = (blockIdx.x * blockDim.x + threadIdx.x) >> 5;
    if (warp >= NI) return;
    int lane = threadIdx.x & 31;
    int half_id = lane >> 4;
    int col8 = lane & 15;

    float acc[8];
#pragma unroll
    for (int k = 0; k < 8; k++) acc[k] = 0.f;

    agg_list_hw(h, g_er, g_off_r[warp], g_off_r[warp + 1], half_id, col8, acc);

#pragma unroll
    for (int k = 0; k < 8; k++)
        acc[k] += __shfl_down_sync(0xffffffff, acc[k], 16);

    if (half_id == 0) {
        float4 b0 = __ldg((const float4*)b + col8 * 2);
        float4 b1 = __ldg((const float4*)b + col8 * 2 + 1);
        float4 o0, o1;
        o0.x = acc[0] + b0.x; o0.y = acc[1] + b0.y;
        o0.z = acc[2] + b0.z; o0.w = acc[3] + b0.w;
        o1.x = acc[4] + b1.x; o1.y = acc[5] + b1.y;
        o1.z = acc[6] + b1.z; o1.w = acc[7] + b1.w;
        if (RELU) {
            o0.x = fmaxf(o0.x, 0.f); o0.y = fmaxf(o0.y, 0.f);
            o0.z = fmaxf(o0.z, 0.f); o0.w = fmaxf(o0.w, 0.f);
            o1.x = fmaxf(o1.x, 0.f); o1.y = fmaxf(o1.y, 0.f);
            o1.z = fmaxf(o1.z, 0.f); o1.w = fmaxf(o1.w, 0.f);
        }
        float4* orow = (float4*)(outp + (size_t)warp * D) + col8 * 2;
        orow[0] = o0;
        orow[1] = o1;
    }
}

// ---------------- host driver --------------------------------------------------

extern "C" void kernel_launch(void* const* d_in, const int* in_sizes, int n_in,
                              void* d_out, int out_size) {
    const float* x_user = (const float*)d_in[0];
    const float* x_item = (const float*)d_in[1];
    const int* f_src = (const int*)d_in[2];
    const int* f_dst = (const int*)d_in[3];
    const int* r_src = (const int*)d_in[4];
    const int* r_dst = (const int*)d_in[5];
    const int* v_src = (const int*)d_in[6];
    const int* v_dst = (const int*)d_in[7];

    const float *W1f, *W1r, *W1v, *W2f, *W2r, *W2v;
    const float *b1f, *b1r, *b1v, *b2f, *b2r, *b2v;
    if (in_sizes[9] == 128 * 128) {
        W1f = (const float*)d_in[8];  W1r = (const float*)d_in[9];  W1v = (const float*)d_in[10];
        W2f = (const float*)d_in[11]; W2r = (const float*)d_in[12]; W2v = (const float*)d_in[13];
        b1f = (const float*)d_in[14]; b1r = (const float*)d_in[15]; b1v = (const float*)d_in[16];
        b2f = (const float*)d_in[17]; b2r = (const float*)d_in[18]; b2v = (const float*)d_in[19];
    } else {
        W1f = (const float*)d_in[8];  b1f = (const float*)d_in[9];
        W1r = (const float*)d_in[10]; b1r = (const float*)d_in[11];
        W1v = (const float*)d_in[12]; b1v = (const float*)d_in[13];
        W2f = (const float*)d_in[14]; b2f = (const float*)d_in[15];
        W2r = (const float*)d_in[16]; b2r = (const float*)d_in[17];
        W2v = (const float*)d_in[18]; b2v = (const float*)d_in[19];
    }
    float* out = (float*)d_out;

    __half *hc1, *hc2, *hu2, *hu2b;
    float *u, *it;
    cudaGetSymbolAddress((void**)&hc1, g_hc1);
    cudaGetSymbolAddress((void**)&hc2, g_hc2);
    cudaGetSymbolAddress((void**)&hu2, g_hu2);
    cudaGetSymbolAddress((void**)&hu2b, g_hu2b);
    cudaGetSymbolAddress((void**)&u,  g_u);
    cudaGetSymbolAddress((void**)&it, g_it);
    __half* hu1 = hc1;
    __half* hi  = hc1 + (size_t)NU * D;
    __half* hu1b = hc2;
    __half* hib  = hc2 + (size_t)NU * D;

    static cudaStream_t s1 = 0, s2 = 0;
    static cudaEvent_t evFork = 0, evCSR = 0, evL1 = 0, evHu2 = 0, evU = 0,
                       evItG = 0, evHu2b = 0, evEnd = 0;
    if (s1 == 0) {
        cudaStreamCreateWithFlags(&s1, cudaStreamNonBlocking);
        cudaStreamCreateWithFlags(&s2, cudaStreamNonBlocking);
        cudaEventCreateWithFlags(&evFork, cudaEventDisableTiming);
        cudaEventCreateWithFlags(&evCSR,  cudaEventDisableTiming);
        cudaEventCreateWithFlags(&evL1,   cudaEventDisableTiming);
        cudaEventCreateWithFlags(&evHu2,  cudaEventDisableTiming);
        cudaEventCreateWithFlags(&evU,    cudaEventDisableTiming);
        cudaEventCreateWithFlags(&evItG,  cudaEventDisableTiming);
        cudaEventCreateWithFlags(&evHu2b, cudaEventDisableTiming);
        cudaEventCreateWithFlags(&evEnd,  cudaEventDisableTiming);
    }

    const int TB = 256;
    cudaFuncSetAttribute(k_gemm, cudaFuncAttributeMaxDynamicSharedMemorySize, GEMM_SMEM);

    int gNU   = (NU + TB - 1) / TB;
    int gAggU = (NU * 32 + TB - 1) / TB;
    int gAggI = (NI * 32 + TB - 1) / TB;
    int nbU = (NU + 1023) / 1024;

    dim3 gEdge3((NE + TB - 1) / TB, 3);
    dim3 gScan1(nbU, 2);
    dim3 gScan3((NU + 1 + TB - 1) / TB, 2);

    // ---- s1: CSR build (DRAM/atomic-bound; overlaps s0 L1 GEMMs) -------------
    cudaEventRecord(evFork, 0);
    cudaStreamWaitEvent(s1, evFork, 0);
    cudaStreamWaitEvent(s2, evFork, 0);
    k_zero_hists<<<gNU, TB, 0, s1>>>();
    k_hist3<<<gEdge3, TB, 0, s1>>>(f_src, f_dst, r_src, r_dst, v_src, v_dst);
    k_inv_all<<<gNU, TB, 0, s1>>>();
    k_scan1<<<gScan1, 1024, 0, s1>>>();
    k_scan2<<<2, 1024, 0, s1>>>();
    k_scan3<<<gScan3, TB, 0, s1>>>();
    k_fill3<<<gEdge3, TB, 0, s1>>>(f_src, f_dst, r_src, r_dst, v_src, v_dst);
    cudaEventRecord(evCSR, s1);

    // ---- s0: user-critical L1 GEMMs first (hu1, hi) ---------------------------
    k_gemm<<<(NU + 63) / 64, 256, GEMM_SMEM>>>(x_user, W1f, hu1, NU);
    k_gemm<<<(NI + 63) / 64, 256, GEMM_SMEM>>>(x_item, W1v, hi,  NI);
    cudaEventRecord(evL1, 0);

    // ---- s2: hu2 GEMM (fma-bound) overlaps agg_user1 (L2-bound) ---------------
    cudaStreamWaitEvent(s2, evL1, 0);
    k_gemm<<<(NU + 63) / 64, 256, GEMM_SMEM, s2>>>(x_user, W1r, hu2, NU);
    cudaEventRecord(evHu2, s2);

    // ---- s0: user chain: agg1 -> W2f -------------------------------------------
    cudaStreamWaitEvent(0, evCSR, 0);
    k_agg_user<true><<<gAggU, TB>>>(hc1, b1f, b1v, u);
    cudaEventRecord(evU, 0);
    k_gemm<<<(NU + 63) / 64, 256, GEMM_SMEM>>>(u, W2f, hu1b, NU);

    // ---- s1: item pipeline (waits hu2 from s2) ----------------------------------
    cudaStreamWaitEvent(s1, evHu2, 0);
    k_agg_item<true><<<gAggI, TB, 0, s1>>>(hu2, b1r, it);
    k_gemm<<<(NI + 63) / 64, 256, GEMM_SMEM, s1>>>(it, W2v, hib, NI);
    cudaEventRecord(evItG, s1);

    // ---- s2: W2r (off s0's critical path; overlaps W2f/agg_user2) ---------------
    cudaStreamWaitEvent(s2, evU, 0);
    k_gemm<<<(NU + 63) / 64, 256, GEMM_SMEM, s2>>>(u, W2r, hu2b, NU);
    cudaEventRecord(evHu2b, s2);

    // ---- s1: final item agg (needs hu2b) -----------------------------------------
    cudaStreamWaitEvent(s1, evHu2b, 0);
    k_agg_item<false><<<gAggI, TB, 0, s1>>>(hu2b, b2r, out + (size_t)NU * D);
    cudaEventRecord(evEnd, s1);

    // ---- s0: final user agg (needs hu1b in-order + hib via evItG) ----------------
    cudaStreamWaitEvent(0, evItG, 0);
    k_agg_user<false><<<gAggU, TB>>>(hc2, b2f, b2v, out);
    cudaStreamWaitEvent(0, evEnd, 0);  // join
}

// round 14
// speedup vs baseline: 1.6379x; 1.0000x over previous
#include <cuda_runtime.h>
#include <cuda_fp16.h>

#define NU 100000
#define NI 50000
#define NE 1600000
#define D  128

// ---------------- scratch (device globals) ----------------------------------
__device__ int g_h_fs[NU];
__device__ int g_h_fd[NU];
__device__ int g_h_rs[NU];
__device__ int g_h_rd[NI];
__device__ int g_h_vs[NI];
__device__ int g_h_vd[NU];

__device__ float g_inv_fs[NU];
__device__ float g_inv_fd[NU];
__device__ float g_inv_rs[NU];
__device__ float g_inv_rd[NI];
__device__ float g_inv_vs[NI];
__device__ float g_inv_vd[NU];

// combined user CSR (follows + rev, fully folded weights), item CSR (rates)
__device__ int   g_off_c[NU + 1];
__device__ int   g_off_r[NI + 1];
__device__ int   g_pos_c[NU];
__device__ int   g_pos_r[NI];
__device__ int2  g_ec[2 * NE];   // {src' (rev: NU+src), w_bits = full coeff}
__device__ int2  g_er[NE];
__device__ int   g_bsum[2][1024];

// layer h-buffers: user rows [0,NU), item rows [NU,NU+NI) contiguous
__device__ __half g_hc1[(size_t)(NU + NI) * D];
__device__ __half g_hc2[(size_t)(NU + NI) * D];
__device__ __half g_hu2 [(size_t)NU * D];
__device__ __half g_hu2b[(size_t)NU * D];
__device__ float  g_u  [(size_t)NU * D];
__device__ float  g_it [(size_t)NI * D];

// ---------------- setup kernels ----------------------------------------------

__global__ void k_zero_hists() {
    int i = blockIdx.x * blockDim.x + threadIdx.x;
    if (i < NU) { g_h_fs[i] = 0; g_h_fd[i] = 0; g_h_rs[i] = 0; g_h_vd[i] = 0; }
    if (i < NI) { g_h_rd[i] = 0; g_h_vs[i] = 0; }
}

__global__ void k_hist3(const int* __restrict__ fs, const int* __restrict__ fd,
                        const int* __restrict__ rs, const int* __restrict__ rd,
                        const int* __restrict__ vs, const int* __restrict__ vd) {
    int e = blockIdx.x * blockDim.x + threadIdx.x;
    if (e >= NE) return;
    if (blockIdx.y == 0) {
        atomicAdd(&g_h_fs[fs[e]], 1);
        atomicAdd(&g_h_fd[fd[e]], 1);
    } else if (blockIdx.y == 1) {
        atomicAdd(&g_h_rs[rs[e]], 1);
        atomicAdd(&g_h_rd[rd[e]], 1);
    } else {
        atomicAdd(&g_h_vs[vs[e]], 1);
        atomicAdd(&g_h_vd[vd[e]], 1);
    }
}

__device__ __forceinline__ float invsq(int x) {
    return x > 0 ? rsqrtf((float)x) : 0.f;
}

__global__ void k_inv_all() {
    int i = blockIdx.x * blockDim.x + threadIdx.x;
    if (i < NU) {
        g_inv_fs[i] = invsq(g_h_fs[i]);
        g_inv_fd[i] = invsq(g_h_fd[i]);
        g_inv_rs[i] = invsq(g_h_rs[i]);
        g_inv_vd[i] = invsq(g_h_vd[i]);
    }
    if (i < NI) {
        g_inv_rd[i] = invsq(g_h_rd[i]);
        g_inv_vs[i] = invsq(g_h_vs[i]);
    }
}

// ---------------- exclusive scan (2 arrays per launch via blockIdx.y) ---------

__global__ void k_scan1() {
    __shared__ int s[1024];
    int tid = threadIdx.x;
    int i = blockIdx.x * 1024 + tid;
    int v;
    int* outp; int n;
    if (blockIdx.y == 0) {
        n = NU; outp = g_off_c;
        v = (i < n) ? (g_h_fd[i] + g_h_vd[i]) : 0;
    } else {
        n = NI; outp = g_off_r;
        v = (i < n) ? g_h_rd[i] : 0;
    }
    s[tid] = v;
    __syncthreads();
#pragma unroll
    for (int o = 1; o < 1024; o <<= 1) {
        int t = (tid >= o) ? s[tid - o] : 0;
        __syncthreads();
        s[tid] += t;
        __syncthreads();
    }
    if (i < n) outp[i] = s[tid] - v;
    if (tid == 1023) g_bsum[blockIdx.y][blockIdx.x] = s[1023];
}

__global__ void k_scan2() {
    __shared__ int s[1024];
    int nb = (blockIdx.x == 1) ? (NI + 1023) / 1024 : (NU + 1023) / 1024;
    int tid = threadIdx.x;
    int v = (tid < nb) ? g_bsum[blockIdx.x][tid] : 0;
    s[tid] = v;
    __syncthreads();
#pragma unroll
    for (int o = 1; o < 1024; o <<= 1) {
        int t = (tid >= o) ? s[tid - o] : 0;
        __syncthreads();
        s[tid] += t;
        __syncthreads();
    }
    if (tid < nb) g_bsum[blockIdx.x][tid] = s[tid] - v;
}

__global__ void k_scan3() {
    int* outp; int* pos; int n; int total;
    if (blockIdx.y == 0) { outp = g_off_c; pos = g_pos_c; n = NU; total = 2 * NE; }
    else                 { outp = g_off_r; pos = g_pos_r; n = NI; total = NE; }
    int i = blockIdx.x * blockDim.x + threadIdx.x;
    if (i < n) {
        int v = outp[i] + g_bsum[blockIdx.y][i >> 10];
        outp[i] = v;
        pos[i] = v;
    } else if (i == n) {
        outp[n] = total;
    }
}

__global__ void k_fill3(const int* __restrict__ fs, const int* __restrict__ fd,
                        const int* __restrict__ rs, const int* __restrict__ rd,
                        const int* __restrict__ vs, const int* __restrict__ vd) {
    int e = blockIdx.x * blockDim.x + threadIdx.x;
    if (e >= NE) return;
    if (blockIdx.y == 0) {
        int s = fs[e], d = fd[e];
        float w = 0.5f * g_inv_fs[s] * g_inv_fd[d];
        int p = atomicAdd(&g_pos_c[d], 1);
        g_ec[p] = make_int2(s, __float_as_int(w));
    } else if (blockIdx.y == 1) {
        int s = rs[e], d = rd[e];
        float w = g_inv_rs[s] * g_inv_rd[d];
        int p = atomicAdd(&g_pos_r[d], 1);
        g_er[p] = make_int2(s, __float_as_int(w));
    } else {
        int s = vs[e], d = vd[e];
        float w = 0.5f * g_inv_vs[s] * g_inv_vd[d];
        int p = atomicAdd(&g_pos_c[d], 1);
        g_ec[p] = make_int2(NU + s, __float_as_int(w));
    }
}

// ---------------- GEMM: C[n,128](fp16) = A[n,128](fp32) @ W[128,128](fp32) ----

#define GEMM_SMEM ((128 * 128 + 128 * 64) * 4)  // W 64KB + At 32KB

__global__ void __launch_bounds__(256) k_gemm(const float* __restrict__ A,
                                              const float* __restrict__ W,
                                              __half* __restrict__ C, int n) {
    extern __shared__ float sm[];
    float* Ws = sm;
    float* At = sm + 128 * 128;

    for (int i = threadIdx.x; i < 128 * 32; i += 256)
        ((float4*)Ws)[i] = ((const float4*)W)[i];

    int row0 = blockIdx.x * 64;
    for (int i = threadIdx.x; i < 64 * 32; i += 256) {
        int c = i >> 6;
        int r = i & 63;
        int row = row0 + r;
        float4 v = (row < n) ? ((const float4*)A)[(size_t)row * 32 + c]
                             : make_float4(0.f, 0.f, 0.f, 0.f);
        At[(4 * c + 0) * 64 + r] = v.x;
        At[(4 * c + 1) * 64 + r] = v.y;
        At[(4 * c + 2) * 64 + r] = v.z;
        At[(4 * c + 3) * 64 + r] = v.w;
    }
    __syncthreads();

    int ty = threadIdx.x >> 5;
    int tx = threadIdx.x & 31;

    unsigned long long acc[4][4];
#pragma unroll
    for (int p = 0; p < 4; p++)
#pragma unroll
        for (int c = 0; c < 4; c++) acc[p][c] = 0ull;

    const float* at = At + ty * 8;
#pragma unroll 8
    for (int k = 0; k < 128; k++) {
        ulonglong2 a01 = *(const ulonglong2*)(at + k * 64);
        ulonglong2 a23 = *(const ulonglong2*)(at + k * 64 + 4);
        float4 wv = ((const float4*)(Ws + k * 128))[tx];
        unsigned long long wb0, wb1, wb2, wb3;
        asm("mov.b64 %0, {%1, %1};" : "=l"(wb0) : "f"(wv.x));
        asm("mov.b64 %0, {%1, %1};" : "=l"(wb1) : "f"(wv.y));
        asm("mov.b64 %0, {%1, %1};" : "=l"(wb2) : "f"(wv.z));
        asm("mov.b64 %0, {%1, %1};" : "=l"(wb3) : "f"(wv.w));
        asm("fma.rn.f32x2 %0, %1, %2, %0;" : "+l"(acc[0][0]) : "l"(a01.x), "l"(wb0));
        asm("fma.rn.f32x2 %0, %1, %2, %0;" : "+l"(acc[0][1]) : "l"(a01.x), "l"(wb1));
        asm("fma.rn.f32x2 %0, %1, %2, %0;" : "+l"(acc[0][2]) : "l"(a01.x), "l"(wb2));
        asm("fma.rn.f32x2 %0, %1, %2, %0;" : "+l"(acc[0][3]) : "l"(a01.x), "l"(wb3));
        asm("fma.rn.f32x2 %0, %1, %2, %0;" : "+l"(acc[1][0]) : "l"(a01.y), "l"(wb0));
        asm("fma.rn.f32x2 %0, %1, %2, %0;" : "+l"(acc[1][1]) : "l"(a01.y), "l"(wb1));
        asm("fma.rn.f32x2 %0, %1, %2, %0;" : "+l"(acc[1][2]) : "l"(a01.y), "l"(wb2));
        asm("fma.rn.f32x2 %0, %1, %2, %0;" : "+l"(acc[1][3]) : "l"(a01.y), "l"(wb3));
        asm("fma.rn.f32x2 %0, %1, %2, %0;" : "+l"(acc[2][0]) : "l"(a23.x), "l"(wb0));
        asm("fma.rn.f32x2 %0, %1, %2, %0;" : "+l"(acc[2][1]) : "l"(a23.x), "l"(wb1));
        asm("fma.rn.f32x2 %0, %1, %2, %0;" : "+l"(acc[2][2]) : "l"(a23.x), "l"(wb2));
        asm("fma.rn.f32x2 %0, %1, %2, %0;" : "+l"(acc[2][3]) : "l"(a23.x), "l"(wb3));
        asm("fma.rn.f32x2 %0, %1, %2, %0;" : "+l"(acc[3][0]) : "l"(a23.y), "l"(wb0));
        asm("fma.rn.f32x2 %0, %1, %2, %0;" : "+l"(acc[3][1]) : "l"(a23.y), "l"(wb1));
        asm("fma.rn.f32x2 %0, %1, %2, %0;" : "+l"(acc[3][2]) : "l"(a23.y), "l"(wb2));
        asm("fma.rn.f32x2 %0, %1, %2, %0;" : "+l"(acc[3][3]) : "l"(a23.y), "l"(wb3));
    }

#pragma unroll
    for (int p = 0; p < 4; p++) {
        float e0, o0, e1, o1, e2, o2, e3, o3;
        asm("mov.b64 {%0, %1}, %2;" : "=f"(e0), "=f"(o0) : "l"(acc[p][0]));
        asm("mov.b64 {%0, %1}, %2;" : "=f"(e1), "=f"(o1) : "l"(acc[p][1]));
        asm("mov.b64 {%0, %1}, %2;" : "=f"(e2), "=f"(o2) : "l"(acc[p][2]));
        asm("mov.b64 {%0, %1}, %2;" : "=f"(e3), "=f"(o3) : "l"(acc[p][3]));
        int row = row0 + ty * 8 + 2 * p;
        if (row < n) {
            __half2 h0 = __floats2half2_rn(e0, e1);
            __half2 h1 = __floats2half2_rn(e2, e3);
            *(uint2*)(C + (size_t)row * D + tx * 4) =
                make_uint2(*(unsigned*)&h0, *(unsigned*)&h1);
        }
        if (row + 1 < n) {
            __half2 h0 = __floats2half2_rn(o0, o1);
            __half2 h1 = __floats2half2_rn(o2, o3);
            *(uint2*)(C + (size_t)(row + 1) * D + tx * 4) =
                make_uint2(*(unsigned*)&h0, *(unsigned*)&h1);
        }
    }
}

// ---------------- CSR gather-aggregate (half-warp per edge, 8-edge unroll) -----

__device__ __forceinline__ void acc8(float* acc, float w, uint4 v) {
    float2 f0 = __half22float2(*(__half2*)&v.x);
    float2 f1 = __half22float2(*(__half2*)&v.y);
    float2 f2 = __half22float2(*(__half2*)&v.z);
    float2 f3 = __half22float2(*(__half2*)&v.w);
    acc[0] += w * f0.x; acc[1] += w * f0.y;
    acc[2] += w * f1.x; acc[3] += w * f1.y;
    acc[4] += w * f2.x; acc[5] += w * f2.y;
    acc[6] += w * f3.x; acc[7] += w * f3.y;
}

__device__ __forceinline__ void agg_list_hw(const __half* __restrict__ h,
                                            const int2* __restrict__ eds,
                                            int j, int end,
                                            int half_id, int col8, float* acc) {
    // 8-edge unrolled main loop: 4 independent gathers in flight per lane
    for (; j + 7 < end; j += 8) {
        int2 e0 = __ldg(eds + j + half_id);
        int2 e1 = __ldg(eds + j + 2 + half_id);
        int2 e2 = __ldg(eds + j + 4 + half_id);
        int2 e3 = __ldg(eds + j + 6 + half_id);
        uint4 v0 = __ldg((const uint4*)(h + (size_t)e0.x * D) + col8);
        uint4 v1 = __ldg((const uint4*)(h + (size_t)e1.x * D) + col8);
        uint4 v2 = __ldg((const uint4*)(h + (size_t)e2.x * D) + col8);
        uint4 v3 = __ldg((const uint4*)(h + (size_t)e3.x * D) + col8);
        acc8(acc, __int_as_float(e0.y), v0);
        acc8(acc, __int_as_float(e1.y), v1);
        acc8(acc, __int_as_float(e2.y), v2);
        acc8(acc, __int_as_float(e3.y), v3);
    }
    if (j + 3 < end) {
        int2 e0 = __ldg(eds + j + half_id);
        int2 e1 = __ldg(eds + j + 2 + half_id);
        uint4 v0 = __ldg((const uint4*)(h + (size_t)e0.x * D) + col8);
        uint4 v1 = __ldg((const uint4*)(h + (size_t)e1.x * D) + col8);
        acc8(acc, __int_as_float(e0.y), v0);
        acc8(acc, __int_as_float(e1.y), v1);
        j += 4;
    }
    if (j + 1 < end) {
        int2 e0 = __ldg(eds + j + half_id);
        uint4 v0 = __ldg((const uint4*)(h + (size_t)e0.x * D) + col8);
        acc8(acc, __int_as_float(e0.y), v0);
        j += 2;
    }
    if (j < end && half_id == 0) {
        int2 e0 = __ldg(eds + j);
        uint4 v0 = __ldg((const uint4*)(h + (size_t)e0.x * D) + col8);
        acc8(acc, __int_as_float(e0.y), v0);
    }
}

template <bool RELU>
__global__ void __launch_bounds__(256) k_agg_user(
    const __half* __restrict__ h,
    const float* __restrict__ bF, const float* __restrict__ bV,
    float* __restrict__ outp) {
    int warp = (blockIdx.x * blockDim.x + threadIdx.x) >> 5;
    if (warp >= NU) return;
    int lane = threadIdx.x & 31;
    int half_id = lane >> 4;
    int col8 = lane & 15;

    float acc[8];
#pragma unroll
    for (int k = 0; k < 8; k++) acc[k] = 0.f;

    agg_list_hw(h, g_ec, g_off_c[warp], g_off_c[warp + 1], half_id, col8, acc);

#pragma unroll
    for (int k = 0; k < 8; k++)
        acc[k] += __shfl_down_sync(0xffffffff, acc[k], 16);

    if (half_id == 0) {
        float4 b10 = __ldg((const float4*)bF + col8 * 2);
        float4 b11 = __ldg((const float4*)bF + col8 * 2 + 1);
        float4 b20 = __ldg((const float4*)bV + col8 * 2);
        float4 b21 = __ldg((const float4*)bV + col8 * 2 + 1);
        float4 o0, o1;
        o0.x = acc[0] + 0.5f * (b10.x + b20.x);
        o0.y = acc[1] + 0.5f * (b10.y + b20.y);
        o0.z = acc[2] + 0.5f * (b10.z + b20.z);
        o0.w = acc[3] + 0.5f * (b10.w + b20.w);
        o1.x = acc[4] + 0.5f * (b11.x + b21.x);
        o1.y = acc[5] + 0.5f * (b11.y + b21.y);
        o1.z = acc[6] + 0.5f * (b11.z + b21.z);
        o1.w = acc[7] + 0.5f * (b11.w + b21.w);
        if (RELU) {
            o0.x = fmaxf(o0.x, 0.f); o0.y = fmaxf(o0.y, 0.f);
            o0.z = fmaxf(o0.z, 0.f); o0.w = fmaxf(o0.w, 0.f);
            o1.x = fmaxf(o1.x, 0.f); o1.y = fmaxf(o1.y, 0.f);
            o1.z = fmaxf(o1.z, 0.f); o1.w = fmaxf(o1.w, 0.f);
        }
        float4* orow = (float4*)(outp + (size_t)warp * D) + col8 * 2;
        orow[0] = o0;
        orow[1] = o1;
    }
}

template <bool RELU>
__global__ void __launch_bounds__(256) k_agg_item(
    const __half* __restrict__ h, const float* __restrict__ b,
    float* __restrict__ outp) {
    int warp = (blockIdx.x * blockDim.x + threadIdx.x) >> 5;
    if (warp >= NI) return;
    int lane = threadIdx.x & 31;
    int half_id = lane >> 4;
    int col8 = lane & 15;

    float acc[8];
#pragma unroll
    for (int k = 0; k < 8; k++) acc[k] = 0.f;

    agg_list_hw(h, g_er, g_off_r[warp], g_off_r[warp + 1], half_id, col8, acc);

#pragma unroll
    for (int k = 0; k < 8; k++)
        acc[k] += __shfl_down_sync(0xffffffff, acc[k], 16);

    if (half_id == 0) {
        float4 b0 = __ldg((const float4*)b + col8 * 2);
        float4 b1 = __ldg((const float4*)b + col8 * 2 + 1);
        float4 o0, o1;
        o0.x = acc[0] + b0.x; o0.y = acc[1] + b0.y;
        o0.z = acc[2] + b0.z; o0.w = acc[3] + b0.w;
        o1.x = acc[4] + b1.x; o1.y = acc[5] + b1.y;
        o1.z = acc[6] + b1.z; o1.w = acc[7] + b1.w;
        if (RELU) {
            o0.x = fmaxf(o0.x, 0.f); o0.y = fmaxf(o0.y, 0.f);
            o0.z = fmaxf(o0.z, 0.f); o0.w = fmaxf(o0.w, 0.f);
            o1.x = fmaxf(o1.x, 0.f); o1.y = fmaxf(o1.y, 0.f);
            o1.z = fmaxf(o1.z, 0.f); o1.w = fmaxf(o1.w, 0.f);
        }
        float4* orow = (float4*)(outp + (size_t)warp * D) + col8 * 2;
        orow[0] = o0;
        orow[1] = o1;
    }
}

// ---------------- host driver --------------------------------------------------

extern "C" void kernel_launch(void* const* d_in, const int* in_sizes, int n_in,
                              void* d_out, int out_size) {
    const float* x_user = (const float*)d_in[0];
    const float* x_item = (const float*)d_in[1];
    const int* f_src = (const int*)d_in[2];
    const int* f_dst = (const int*)d_in[3];
    const int* r_src = (const int*)d_in[4];
    const int* r_dst = (const int*)d_in[5];
    const int* v_src = (const int*)d_in[6];
    const int* v_dst = (const int*)d_in[7];

    const float *W1f, *W1r, *W1v, *W2f, *W2r, *W2v;
    const float *b1f, *b1r, *b1v, *b2f, *b2r, *b2v;
    if (in_sizes[9] == 128 * 128) {
        W1f = (const float*)d_in[8];  W1r = (const float*)d_in[9];  W1v = (const float*)d_in[10];
        W2f = (const float*)d_in[11]; W2r = (const float*)d_in[12]; W2v = (const float*)d_in[13];
        b1f = (const float*)d_in[14]; b1r = (const float*)d_in[15]; b1v = (const float*)d_in[16];
        b2f = (const float*)d_in[17]; b2r = (const float*)d_in[18]; b2v = (const float*)d_in[19];
    } else {
        W1f = (const float*)d_in[8];  b1f = (const float*)d_in[9];
        W1r = (const float*)d_in[10]; b1r = (const float*)d_in[11];
        W1v = (const float*)d_in[12]; b1v = (const float*)d_in[13];
        W2f = (const float*)d_in[14]; b2f = (const float*)d_in[15];
        W2r = (const float*)d_in[16]; b2r = (const float*)d_in[17];
        W2v = (const float*)d_in[18]; b2v = (const float*)d_in[19];
    }
    float* out = (float*)d_out;

    __half *hc1, *hc2, *hu2, *hu2b;
    float *u, *it;
    cudaGetSymbolAddress((void**)&hc1, g_hc1);
    cudaGetSymbolAddress((void**)&hc2, g_hc2);
    cudaGetSymbolAddress((void**)&hu2, g_hu2);
    cudaGetSymbolAddress((void**)&hu2b, g_hu2b);
    cudaGetSymbolAddress((void**)&u,  g_u);
    cudaGetSymbolAddress((void**)&it, g_it);
    __half* hu1 = hc1;
    __half* hi  = hc1 + (size_t)NU * D;
    __half* hu1b = hc2;
    __half* hib  = hc2 + (size_t)NU * D;

    static cudaStream_t s1 = 0, s2 = 0;
    static cudaEvent_t evFork = 0, evCSR = 0, evL1 = 0, evHu2 = 0, evU = 0,
                       evItG = 0, evHu2b = 0, evEnd = 0;
    if (s1 == 0) {
        cudaStreamCreateWithFlags(&s1, cudaStreamNonBlocking);
        cudaStreamCreateWithFlags(&s2, cudaStreamNonBlocking);
        cudaEventCreateWithFlags(&evFork, cudaEventDisableTiming);
        cudaEventCreateWithFlags(&evCSR,  cudaEventDisableTiming);
        cudaEventCreateWithFlags(&evL1,   cudaEventDisableTiming);
        cudaEventCreateWithFlags(&evHu2,  cudaEventDisableTiming);
        cudaEventCreateWithFlags(&evU,    cudaEventDisableTiming);
        cudaEventCreateWithFlags(&evItG,  cudaEventDisableTiming);
        cudaEventCreateWithFlags(&evHu2b, cudaEventDisableTiming);
        cudaEventCreateWithFlags(&evEnd,  cudaEventDisableTiming);
    }

    const int TB = 256;
    cudaFuncSetAttribute(k_gemm, cudaFuncAttributeMaxDynamicSharedMemorySize, GEMM_SMEM);

    int gNU   = (NU + TB - 1) / TB;
    int gAggU = (NU * 32 + TB - 1) / TB;
    int gAggI = (NI * 32 + TB - 1) / TB;
    int nbU = (NU + 1023) / 1024;

    dim3 gEdge3((NE + TB - 1) / TB, 3);
    dim3 gScan1(nbU, 2);
    dim3 gScan3((NU + 1 + TB - 1) / TB, 2);

    // ---- s1: CSR build (overlaps s0 L1 GEMMs) --------------------------------
    cudaEventRecord(evFork, 0);
    cudaStreamWaitEvent(s1, evFork, 0);
    cudaStreamWaitEvent(s2, evFork, 0);
    k_zero_hists<<<gNU, TB, 0, s1>>>();
    k_hist3<<<gEdge3, TB, 0, s1>>>(f_src, f_dst, r_src, r_dst, v_src, v_dst);
    k_inv_all<<<gNU, TB, 0, s1>>>();
    k_scan1<<<gScan1, 1024, 0, s1>>>();
    k_scan2<<<2, 1024, 0, s1>>>();
    k_scan3<<<gScan3, TB, 0, s1>>>();
    k_fill3<<<gEdge3, TB, 0, s1>>>(f_src, f_dst, r_src, r_dst, v_src, v_dst);
    cudaEventRecord(evCSR, s1);

    // ---- s0: user-critical L1 GEMMs (hu1, hi) ----------------------------------
    k_gemm<<<(NU + 63) / 64, 256, GEMM_SMEM>>>(x_user, W1f, hu1, NU);
    k_gemm<<<(NI + 63) / 64, 256, GEMM_SMEM>>>(x_item, W1v, hi,  NI);
    cudaEventRecord(evL1, 0);

    // ---- s2: hu2 GEMM overlaps agg_user1 ----------------------------------------
    cudaStreamWaitEvent(s2, evL1, 0);
    k_gemm<<<(NU + 63) / 64, 256, GEMM_SMEM, s2>>>(x_user, W1r, hu2, NU);
    cudaEventRecord(evHu2, s2);

    // ---- s0: user chain: agg1 -> W2f ---------------------------------------------
    cudaStreamWaitEvent(0, evCSR, 0);
    k_agg_user<true><<<gAggU, TB>>>(hc1, b1f, b1v, u);
    cudaEventRecord(evU, 0);
    k_gemm<<<(NU + 63) / 64, 256, GEMM_SMEM>>>(u, W2f, hu1b, NU);

    // ---- s1: item pipeline ---------------------------------------------------------
    cudaStreamWaitEvent(s1, evHu2, 0);
    k_agg_item<true><<<gAggI, TB, 0, s1>>>(hu2, b1r, it);
    k_gemm<<<(NI + 63) / 64, 256, GEMM_SMEM, s1>>>(it, W2v, hib, NI);
    cudaEventRecord(evItG, s1);

    // ---- s2: W2r overlaps W2f/agg_user2 ---------------------------------------------
    cudaStreamWaitEvent(s2, evU, 0);
    k_gemm<<<(NU + 63) / 64, 256, GEMM_SMEM, s2>>>(u, W2r, hu2b, NU);
    cudaEventRecord(evHu2b, s2);

    // ---- s1: final item agg -----------------------------------------------------------
    cudaStreamWaitEvent(s1, evHu2b, 0);
    k_agg_item<false><<<gAggI, TB, 0, s1>>>(hu2b, b2r, out + (size_t)NU * D);
    cudaEventRecord(evEnd, s1);

    // ---- s0: final user agg --------------------------------------------------------------
    cudaStreamWaitEvent(0, evItG, 0);
    k_agg_user<false><<<gAggU, TB>>>(hc2, b2f, b2v, out);
    cudaStreamWaitEvent(0, evEnd, 0);  // join
}